// round 1
// baseline (speedup 1.0000x reference)
#include <cuda_runtime.h>
#include <math.h>

#define BB 32
#define CC 512
#define NN 1024      // H*W = 32*32
#define HEADS 8
#define HD 64
#define BN_EPS 1e-5f

// ---------------- scratch (device globals; no allocation allowed) ----------------
__device__ float g_Q[(size_t)BB * CC * NN];
__device__ float g_K[(size_t)BB * CC * NN];
__device__ float g_V[(size_t)BB * CC * NN];
__device__ float g_G[(size_t)BB * CC * NN];
__device__ float g_O[(size_t)BB * CC * NN];
__device__ float g_attn[(size_t)BB * HEADS * HD * HD];
__device__ float g_bnsum[CC];
__device__ float g_bnsum2[CC];

// ---------------- zero BN accumulators ----------------
__global__ void zero_bn_kernel() {
    int t = threadIdx.x;
    if (t < CC) { g_bnsum[t] = 0.f; g_bnsum2[t] = 0.f; }
}

// ---------------- fp32 SGEMM: Y[b] (512x1024) = W (512x512) @ X[b] (512x1024) (+bias) ----
// 128x128 tile, BK=8, 256 threads, 8x8 per-thread micro-tile
__global__ __launch_bounds__(256)
void sgemm_kernel(const float* __restrict__ Wm, const float* __restrict__ X,
                  float* __restrict__ Y, const float* __restrict__ bias)
{
    const int b  = blockIdx.z;
    const int m0 = blockIdx.y * 128;
    const int n0 = blockIdx.x * 128;
    const float* Xb = X + (size_t)b * CC * NN;
    float*       Yb = Y + (size_t)b * CC * NN;

    __shared__ float As[8][128];   // [k][m]
    __shared__ float Bs[8][128];   // [k][n]

    const int tid = threadIdx.x;
    const int am  = tid >> 1;           // 0..127
    const int ak  = (tid & 1) * 4;      // 0 or 4
    const int bk  = tid >> 5;           // 0..7
    const int bn  = (tid & 31) * 4;     // 0..124

    const int tm = (tid / 16) * 8;
    const int tn = (tid % 16) * 8;

    float acc[8][8];
    #pragma unroll
    for (int i = 0; i < 8; i++)
        #pragma unroll
        for (int j = 0; j < 8; j++) acc[i][j] = 0.f;

    for (int k0 = 0; k0 < CC; k0 += 8) {
        float4 av = *(const float4*)(Wm + (size_t)(m0 + am) * CC + k0 + ak);
        float4 bv = *(const float4*)(Xb + (size_t)(k0 + bk) * NN + n0 + bn);
        As[ak + 0][am] = av.x; As[ak + 1][am] = av.y;
        As[ak + 2][am] = av.z; As[ak + 3][am] = av.w;
        *(float4*)&Bs[bk][bn] = bv;
        __syncthreads();

        #pragma unroll
        for (int kk = 0; kk < 8; kk++) {
            float ar[8], br[8];
            #pragma unroll
            for (int i = 0; i < 8; i++) ar[i] = As[kk][tm + i];
            #pragma unroll
            for (int j = 0; j < 8; j++) br[j] = Bs[kk][tn + j];
            #pragma unroll
            for (int i = 0; i < 8; i++)
                #pragma unroll
                for (int j = 0; j < 8; j++)
                    acc[i][j] += ar[i] * br[j];
        }
        __syncthreads();
    }

    #pragma unroll
    for (int i = 0; i < 8; i++) {
        float bi = bias ? bias[m0 + tm + i] : 0.f;
        #pragma unroll
        for (int j = 0; j < 8; j += 4) {
            float4 v = make_float4(acc[i][j] + bi, acc[i][j + 1] + bi,
                                   acc[i][j + 2] + bi, acc[i][j + 3] + bi);
            *(float4*)(Yb + (size_t)(m0 + tm + i) * NN + n0 + tn + j) = v;
        }
    }
}

// ---------------- L2 normalize each (b,c) row over N ----------------
__global__ void l2norm_kernel(float* __restrict__ buf)
{
    const int row = blockIdx.x;                 // b*C + c
    float* p = buf + (size_t)row * NN;
    const int t = threadIdx.x;                  // 256
    float ss = 0.f;
    for (int i = t; i < NN; i += 256) { float v = p[i]; ss += v * v; }
    __shared__ float red[256];
    red[t] = ss; __syncthreads();
    for (int s = 128; s > 0; s >>= 1) {
        if (t < s) red[t] += red[t + s];
        __syncthreads();
    }
    const float inv = 1.0f / fmaxf(sqrtf(red[0]), 1e-12f);
    for (int i = t; i < NN; i += 256) p[i] *= inv;
}

// ---------------- attn = softmax( Qn @ Kn^T * temp ) per (b,h) ----------------
__global__ __launch_bounds__(256)
void attn_kernel(const float* __restrict__ Q, const float* __restrict__ K,
                 const float* __restrict__ temp, float* __restrict__ attn)
{
    const int bh = blockIdx.x;                  // b*HEADS + h
    const int b = bh / HEADS, h = bh % HEADS;
    const float* Qb = Q + (size_t)b * CC * NN + (size_t)h * HD * NN;
    const float* Kb = K + (size_t)b * CC * NN + (size_t)h * HD * NN;

    __shared__ float Qs[64][64];
    __shared__ float Ks[64][64];
    float* Ss = &Qs[0][0];                      // reuse after compute (64x64, stride 64)

    const int t  = threadIdx.x;
    const int tx = t % 16, ty = t / 16;

    float acc[4][4];
    #pragma unroll
    for (int i = 0; i < 4; i++)
        #pragma unroll
        for (int j = 0; j < 4; j++) acc[i][j] = 0.f;

    for (int n0 = 0; n0 < NN; n0 += 64) {
        for (int i = t; i < 64 * 64; i += 256) {
            int r = i >> 6, cidx = i & 63;
            Qs[r][cidx] = Qb[(size_t)r * NN + n0 + cidx];
            Ks[r][cidx] = Kb[(size_t)r * NN + n0 + cidx];
        }
        __syncthreads();
        #pragma unroll 8
        for (int nn = 0; nn < 64; nn++) {
            float a[4], bb[4];
            #pragma unroll
            for (int i = 0; i < 4; i++) a[i]  = Qs[ty * 4 + i][nn];
            #pragma unroll
            for (int j = 0; j < 4; j++) bb[j] = Ks[tx * 4 + j][nn];
            #pragma unroll
            for (int i = 0; i < 4; i++)
                #pragma unroll
                for (int j = 0; j < 4; j++)
                    acc[i][j] += a[i] * bb[j];
        }
        __syncthreads();
    }

    const float tmp = temp[h];
    #pragma unroll
    for (int i = 0; i < 4; i++)
        #pragma unroll
        for (int j = 0; j < 4; j++)
            Ss[(ty * 4 + i) * 64 + (tx * 4 + j)] = acc[i][j] * tmp;
    __syncthreads();

    if (t < 64) {
        float mx = -1e30f;
        for (int e = 0; e < 64; e++) mx = fmaxf(mx, Ss[t * 64 + e]);
        float sum = 0.f;
        for (int e = 0; e < 64; e++) {
            float ev = expf(Ss[t * 64 + e] - mx);
            Ss[t * 64 + e] = ev; sum += ev;
        }
        float inv = 1.f / sum;
        float* out = attn + ((size_t)bh * HD + t) * HD;
        for (int e = 0; e < 64; e++) out[e] = Ss[t * 64 + e] * inv;
    }
}

// ---------------- depthwise 3x3 conv + per-channel sum/sumsq ----------------
__global__ __launch_bounds__(256)
void dwconv_kernel(const float* __restrict__ x, const float* __restrict__ dw,
                   float* __restrict__ g)
{
    const int bc = blockIdx.x;                  // b*C + c
    const int c  = bc % CC;
    const float* img = x + (size_t)bc * NN;

    __shared__ float sm[34][34];
    const int t = threadIdx.x;                  // 256
    for (int i = t; i < 34 * 34; i += 256) {
        int yy = i / 34 - 1, xx = i % 34 - 1;
        sm[i / 34][i % 34] =
            (yy >= 0 && yy < 32 && xx >= 0 && xx < 32) ? img[yy * 32 + xx] : 0.f;
    }
    float w[9];
    #pragma unroll
    for (int i = 0; i < 9; i++) w[i] = dw[c * 9 + i];
    __syncthreads();

    float s = 0.f, s2 = 0.f;
    for (int p = t; p < NN; p += 256) {
        int y = p >> 5, xx = p & 31;
        float acc = 0.f;
        #pragma unroll
        for (int dy = 0; dy < 3; dy++)
            #pragma unroll
            for (int dx = 0; dx < 3; dx++)
                acc += sm[y + dy][xx + dx] * w[dy * 3 + dx];
        g[(size_t)bc * NN + p] = acc;
        s += acc; s2 += acc * acc;
    }

    __shared__ float r1[256], r2[256];
    r1[t] = s; r2[t] = s2; __syncthreads();
    for (int st = 128; st > 0; st >>= 1) {
        if (t < st) { r1[t] += r1[t + st]; r2[t] += r2[t + st]; }
        __syncthreads();
    }
    if (t == 0) { atomicAdd(&g_bnsum[c], r1[0]); atomicAdd(&g_bnsum2[c], r2[0]); }
}

// ---------------- BN(batch stats) + SiLU, then V *= gate ----------------
__global__ void bn_silu_mul_kernel(const float* __restrict__ g,
                                   const float* __restrict__ gamma,
                                   const float* __restrict__ beta,
                                   float* __restrict__ v)
{
    const size_t idx = (size_t)blockIdx.x * 256 + threadIdx.x;  // B*C*N total
    const int c = (int)((idx / NN) % CC);
    const float cnt  = (float)(BB * NN);
    const float mean = g_bnsum[c] / cnt;
    const float var  = g_bnsum2[c] / cnt - mean * mean;
    float gn = (g[idx] - mean) * rsqrtf(var + BN_EPS) * gamma[c] + beta[c];
    float sil = gn / (1.f + __expf(-gn));
    v[idx] *= sil;
}

// ---------------- O[b,h] (64x1024) = attn[b,h] (64x64) @ V[b,h] (64x1024) ----------------
__global__ __launch_bounds__(256)
void attn_apply_kernel(const float* __restrict__ attn, const float* __restrict__ v,
                       float* __restrict__ o)
{
    const int bh = blockIdx.x;
    const int n  = blockIdx.y * 256 + threadIdx.x;
    const int b = bh / HEADS, h = bh % HEADS;
    const float* A  = attn + (size_t)bh * HD * HD;
    const float* Vb = v + (size_t)b * CC * NN + (size_t)h * HD * NN;
    float*       Ob = o + (size_t)b * CC * NN + (size_t)h * HD * NN;

    __shared__ float As[64 * 64];
    for (int i = threadIdx.x; i < 64 * 64; i += 256) As[i] = A[i];
    __syncthreads();

    float acc[64];
    #pragma unroll
    for (int d = 0; d < 64; d++) acc[d] = 0.f;

    #pragma unroll 4
    for (int e = 0; e < 64; e++) {
        float ve = Vb[(size_t)e * NN + n];
        #pragma unroll
        for (int d = 0; d < 64; d++) acc[d] += As[d * 64 + e] * ve;
    }
    #pragma unroll
    for (int d = 0; d < 64; d++) Ob[(size_t)d * NN + n] = acc[d];
}

// ---------------- launch ----------------
extern "C" void kernel_launch(void* const* d_in, const int* in_sizes, int n_in,
                              void* d_out, int out_size)
{
    const float* x     = (const float*)d_in[0];
    const float* Wq    = (const float*)d_in[1];
    const float* Wk    = (const float*)d_in[2];
    const float* Wv    = (const float*)d_in[3];
    const float* dw_w  = (const float*)d_in[4];
    const float* gamma = (const float*)d_in[5];
    const float* beta  = (const float*)d_in[6];
    const float* temp  = (const float*)d_in[7];
    const float* Wp    = (const float*)d_in[8];
    const float* bp    = (const float*)d_in[9];
    float* out = (float*)d_out;

    float *Qb, *Kb, *Vb, *Gb, *Ob, *Ab;
    cudaGetSymbolAddress((void**)&Qb, g_Q);
    cudaGetSymbolAddress((void**)&Kb, g_K);
    cudaGetSymbolAddress((void**)&Vb, g_V);
    cudaGetSymbolAddress((void**)&Gb, g_G);
    cudaGetSymbolAddress((void**)&Ob, g_O);
    cudaGetSymbolAddress((void**)&Ab, g_attn);

    zero_bn_kernel<<<1, 512>>>();

    dim3 gemm_grid(NN / 128, CC / 128, BB);   // (8,4,32)
    sgemm_kernel<<<gemm_grid, 256>>>(Wq, x, Qb, nullptr);
    sgemm_kernel<<<gemm_grid, 256>>>(Wk, x, Kb, nullptr);
    sgemm_kernel<<<gemm_grid, 256>>>(Wv, x, Vb, nullptr);

    l2norm_kernel<<<BB * CC, 256>>>(Qb);
    l2norm_kernel<<<BB * CC, 256>>>(Kb);

    attn_kernel<<<BB * HEADS, 256>>>(Qb, Kb, temp, Ab);

    dwconv_kernel<<<BB * CC, 256>>>(x, dw_w, Gb);
    bn_silu_mul_kernel<<<(BB * CC * NN) / 256, 256>>>(Gb, gamma, beta, Vb);

    attn_apply_kernel<<<dim3(BB * HEADS, NN / 256), 256>>>(Ab, Vb, Ob);

    sgemm_kernel<<<gemm_grid, 256>>>(Wp, Ob, out, bp);
}

// round 3
// speedup vs baseline: 1.3730x; 1.3730x over previous
#include <cuda_runtime.h>
#include <math.h>
#include <stdint.h>

#define BB 32
#define CC 512
#define NN 1024      // H*W = 32*32
#define HEADS 8
#define HD 64
#define BN_EPS 1e-5f

// ---------------- scratch (device globals; no allocation allowed) ----------------
__device__ float g_Q[(size_t)BB * CC * NN];
__device__ float g_K[(size_t)BB * CC * NN];
__device__ float g_V[(size_t)BB * CC * NN];
__device__ float g_G[(size_t)BB * CC * NN];
__device__ float g_O[(size_t)BB * CC * NN];
__device__ float g_attn[(size_t)BB * HEADS * HD * HD];
__device__ float g_bnsum[CC];
__device__ float g_bnsum2[CC];

// ============================ helpers ============================
__device__ __forceinline__ uint32_t smem_u32(const void* p) {
    uint32_t a;
    asm("{ .reg .u64 t; cvta.to.shared.u64 t, %1; cvt.u32.u64 %0, t; }" : "=r"(a) : "l"(p));
    return a;
}
__device__ __forceinline__ void cp_async16(uint32_t dst, const void* src) {
    asm volatile("cp.async.cg.shared.global [%0], [%1], 16;" :: "r"(dst), "l"(src));
}
#define CP_COMMIT() asm volatile("cp.async.commit_group;" ::: "memory")
#define CP_WAIT(n)  asm volatile("cp.async.wait_group %0;" :: "n"(n) : "memory")

__device__ __forceinline__ uint32_t to_tf32(float f) {
    uint32_t r;
    asm("cvt.rna.tf32.f32 %0, %1;" : "=r"(r) : "f"(f));
    return r;
}
__device__ __forceinline__ void mma_tf32(float* c, const uint32_t* a, const uint32_t* b) {
    asm volatile("mma.sync.aligned.m16n8k8.row.col.f32.tf32.tf32.f32 "
        "{%0,%1,%2,%3}, {%4,%5,%6,%7}, {%8,%9}, {%0,%1,%2,%3};"
        : "+f"(c[0]), "+f"(c[1]), "+f"(c[2]), "+f"(c[3])
        : "r"(a[0]), "r"(a[1]), "r"(a[2]), "r"(a[3]), "r"(b[0]), "r"(b[1]));
}

// ============================ kernels ============================
__global__ void zero_bn_kernel() {
    int t = threadIdx.x;
    if (t < CC) { g_bnsum[t] = 0.f; g_bnsum2[t] = 0.f; }
}

// ---- tf32 tensor GEMM: Y[b](512x1024) = W(512x512) @ X[b](512x1024) (+bias) ----
// tile 128x128, BK=16, 256 threads (8 warps, 4(M) x 2(N)), warp tile 32x64
#define BSTRIDE 136
__global__ __launch_bounds__(256)
void gemm_mma(const float* __restrict__ W, const float* __restrict__ X,
              float* __restrict__ Y, const float* __restrict__ bias)
{
    __shared__ float As[2][128 * 16];        // [m][k] with float4-level XOR swizzle
    __shared__ float Bs[2][16 * BSTRIDE];    // [k][n] padded

    const int t    = threadIdx.x;
    const int lane = t & 31;
    const int wid  = t >> 5;
    const int wm   = wid & 3;                // 0..3 -> M offset 32*wm
    const int wn   = wid >> 2;               // 0..1 -> N offset 64*wn
    const int m0   = blockIdx.y * 128;
    const int n0   = blockIdx.x * 128;
    const int b    = blockIdx.z;

    const float* Ag = W + (size_t)m0 * CC;
    const float* Bg = X + (size_t)b * CC * NN + n0;
    float*       Yb = Y + (size_t)b * CC * NN;

    const uint32_t AsU[2] = { smem_u32(As[0]), smem_u32(As[1]) };
    const uint32_t BsU[2] = { smem_u32(Bs[0]), smem_u32(Bs[1]) };

    float acc[2][8][4];
    #pragma unroll
    for (int i = 0; i < 2; i++)
        #pragma unroll
        for (int j = 0; j < 8; j++)
            #pragma unroll
            for (int q = 0; q < 4; q++) acc[i][j][q] = 0.f;

    // stage loader: A 128x16 (swizzled), B 16x128 (padded)
    auto ld_stage = [&](int s, int k0) {
        #pragma unroll
        for (int i = 0; i < 2; i++) {
            int idx = t + 256 * i;
            int r = idx >> 2, j = idx & 3;
            uint32_t dst = AsU[s] + (uint32_t)(r * 16 + ((j ^ (r & 3)) << 2)) * 4u;
            cp_async16(dst, Ag + (size_t)r * CC + k0 + j * 4);
        }
        #pragma unroll
        for (int i = 0; i < 2; i++) {
            int idx = t + 256 * i;
            int r = idx >> 5, j = idx & 31;
            uint32_t dst = BsU[s] + (uint32_t)(r * BSTRIDE + j * 4) * 4u;
            cp_async16(dst, Bg + (size_t)(k0 + r) * NN + j * 4);
        }
    };

    ld_stage(0, 0);
    CP_COMMIT();

    const int gid = lane >> 2, tig = lane & 3;

    for (int c = 0; c < 32; c++) {
        if (c < 31) { ld_stage((c + 1) & 1, (c + 1) * 16); CP_COMMIT(); CP_WAIT(1); }
        else        { CP_WAIT(0); }
        __syncthreads();

        const float* Ac = As[c & 1];
        const float* Bc = Bs[c & 1];

        #pragma unroll
        for (int ks = 0; ks < 2; ks++) {
            uint32_t afr[2][4];
            #pragma unroll
            for (int i = 0; i < 2; i++) {
                int m  = wm * 32 + i * 16 + gid;
                int m8 = m + 8;
                int j0 = ks * 2, j1 = ks * 2 + 1;
                afr[i][0] = to_tf32(Ac[m  * 16 + ((j0 ^ (m  & 3)) << 2) + tig]);
                afr[i][1] = to_tf32(Ac[m8 * 16 + ((j0 ^ (m8 & 3)) << 2) + tig]);
                afr[i][2] = to_tf32(Ac[m  * 16 + ((j1 ^ (m  & 3)) << 2) + tig]);
                afr[i][3] = to_tf32(Ac[m8 * 16 + ((j1 ^ (m8 & 3)) << 2) + tig]);
            }
            uint32_t bfr[8][2];
            const int kr = ks * 8 + tig;
            const int nb = wn * 64 + gid;
            #pragma unroll
            for (int j = 0; j < 8; j++) {
                bfr[j][0] = to_tf32(Bc[kr       * BSTRIDE + nb + j * 8]);
                bfr[j][1] = to_tf32(Bc[(kr + 4) * BSTRIDE + nb + j * 8]);
            }
            #pragma unroll
            for (int i = 0; i < 2; i++)
                #pragma unroll
                for (int j = 0; j < 8; j++)
                    mma_tf32(acc[i][j], afr[i], bfr[j]);
        }
        __syncthreads();
    }

    // epilogue
    #pragma unroll
    for (int i = 0; i < 2; i++) {
        int m = m0 + wm * 32 + i * 16 + gid;
        float b0 = bias ? bias[m] : 0.f;
        float b1 = bias ? bias[m + 8] : 0.f;
        float* r0 = Yb + (size_t)m * NN + n0 + wn * 64;
        float* r1 = r0 + 8 * NN;
        #pragma unroll
        for (int j = 0; j < 8; j++) {
            int cb = j * 8 + 2 * tig;
            *(float2*)(r0 + cb) = make_float2(acc[i][j][0] + b0, acc[i][j][1] + b0);
            *(float2*)(r1 + cb) = make_float2(acc[i][j][2] + b1, acc[i][j][3] + b1);
        }
    }
}

// ---------------- L2 normalize each (b,c) row over N ----------------
__global__ void l2norm_kernel(float* __restrict__ buf)
{
    const int row = blockIdx.x;
    float* p = buf + (size_t)row * NN;
    const int t = threadIdx.x;
    float ss = 0.f;
    for (int i = t; i < NN; i += 256) { float v = p[i]; ss += v * v; }
    __shared__ float red[256];
    red[t] = ss; __syncthreads();
    for (int s = 128; s > 0; s >>= 1) {
        if (t < s) red[t] += red[t + s];
        __syncthreads();
    }
    const float inv = 1.0f / fmaxf(sqrtf(red[0]), 1e-12f);
    for (int i = t; i < NN; i += 256) p[i] *= inv;
}

// ---------------- attn = softmax( Qn @ Kn^T * temp ) per (b,h) ----------------
__global__ __launch_bounds__(256)
void attn_kernel(const float* __restrict__ Q, const float* __restrict__ K,
                 const float* __restrict__ temp, float* __restrict__ attn)
{
    const int bh = blockIdx.x;
    const int b = bh / HEADS, h = bh % HEADS;
    const float* Qb = Q + (size_t)b * CC * NN + (size_t)h * HD * NN;
    const float* Kb = K + (size_t)b * CC * NN + (size_t)h * HD * NN;

    __shared__ float Qs[64][64];
    __shared__ float Ks[64][64];
    float* Ss = &Qs[0][0];

    const int t = threadIdx.x;
    const int tx = t % 16, ty = t / 16;

    float acc[4][4];
    #pragma unroll
    for (int i = 0; i < 4; i++)
        #pragma unroll
        for (int j = 0; j < 4; j++) acc[i][j] = 0.f;

    for (int n0 = 0; n0 < NN; n0 += 64) {
        for (int i = t; i < 64 * 64; i += 256) {
            int r = i >> 6, cidx = i & 63;
            Qs[r][cidx] = Qb[(size_t)r * NN + n0 + cidx];
            Ks[r][cidx] = Kb[(size_t)r * NN + n0 + cidx];
        }
        __syncthreads();
        #pragma unroll 8
        for (int nn = 0; nn < 64; nn++) {
            float a[4], bb2[4];
            #pragma unroll
            for (int i = 0; i < 4; i++) a[i] = Qs[ty * 4 + i][nn];
            #pragma unroll
            for (int j = 0; j < 4; j++) bb2[j] = Ks[tx * 4 + j][nn];
            #pragma unroll
            for (int i = 0; i < 4; i++)
                #pragma unroll
                for (int j = 0; j < 4; j++)
                    acc[i][j] += a[i] * bb2[j];
        }
        __syncthreads();
    }

    const float tmp = temp[h];
    #pragma unroll
    for (int i = 0; i < 4; i++)
        #pragma unroll
        for (int j = 0; j < 4; j++)
            Ss[(ty * 4 + i) * 64 + (tx * 4 + j)] = acc[i][j] * tmp;
    __syncthreads();

    if (t < 64) {
        float mx = -1e30f;
        for (int e = 0; e < 64; e++) mx = fmaxf(mx, Ss[t * 64 + e]);
        float sum = 0.f;
        for (int e = 0; e < 64; e++) {
            float ev = expf(Ss[t * 64 + e] - mx);
            Ss[t * 64 + e] = ev; sum += ev;
        }
        float inv = 1.f / sum;
        float* out = attn + ((size_t)bh * HD + t) * HD;
        for (int e = 0; e < 64; e++) out[e] = Ss[t * 64 + e] * inv;
    }
}

// ---------------- depthwise 3x3 conv + per-channel sum/sumsq ----------------
__global__ __launch_bounds__(256)
void dwconv_kernel(const float* __restrict__ x, const float* __restrict__ dw,
                   float* __restrict__ g)
{
    const int bc = blockIdx.x;
    const int c = bc % CC;
    const float* img = x + (size_t)bc * NN;

    __shared__ float sm[34][34];
    const int t = threadIdx.x;
    for (int i = t; i < 34 * 34; i += 256) {
        int yy = i / 34 - 1, xx = i % 34 - 1;
        sm[i / 34][i % 34] =
            (yy >= 0 && yy < 32 && xx >= 0 && xx < 32) ? img[yy * 32 + xx] : 0.f;
    }
    float w[9];
    #pragma unroll
    for (int i = 0; i < 9; i++) w[i] = dw[c * 9 + i];
    __syncthreads();

    float s = 0.f, s2 = 0.f;
    for (int p = t; p < NN; p += 256) {
        int y = p >> 5, xx = p & 31;
        float acc = 0.f;
        #pragma unroll
        for (int dy = 0; dy < 3; dy++)
            #pragma unroll
            for (int dx = 0; dx < 3; dx++)
                acc += sm[y + dy][xx + dx] * w[dy * 3 + dx];
        g[(size_t)bc * NN + p] = acc;
        s += acc; s2 += acc * acc;
    }

    __shared__ float r1[256], r2[256];
    r1[t] = s; r2[t] = s2; __syncthreads();
    for (int st = 128; st > 0; st >>= 1) {
        if (t < st) { r1[t] += r1[t + st]; r2[t] += r2[t + st]; }
        __syncthreads();
    }
    if (t == 0) { atomicAdd(&g_bnsum[c], r1[0]); atomicAdd(&g_bnsum2[c], r2[0]); }
}

// ---------------- BN(batch stats) + SiLU, then V *= gate ----------------
__global__ void bn_silu_mul_kernel(const float* __restrict__ g,
                                   const float* __restrict__ gamma,
                                   const float* __restrict__ beta,
                                   float* __restrict__ v)
{
    const size_t idx = (size_t)blockIdx.x * 256 + threadIdx.x;
    const int c = (int)((idx / NN) % CC);
    const float cnt = (float)(BB * NN);
    const float mean = g_bnsum[c] / cnt;
    const float var = g_bnsum2[c] / cnt - mean * mean;
    float gn = (g[idx] - mean) * rsqrtf(var + BN_EPS) * gamma[c] + beta[c];
    float sil = gn / (1.f + __expf(-gn));
    v[idx] *= sil;
}

// ---- O[b,h] (64x1024) = attn[b,h] (64x64) @ V[b,h] (64x1024) ----
__global__ __launch_bounds__(256)
void attn_apply_kernel(const float* __restrict__ attn, const float* __restrict__ v,
                       float* __restrict__ o)
{
    const int bh = blockIdx.x;
    const int n = blockIdx.y * 256 + threadIdx.x;
    const int b = bh / HEADS, h = bh % HEADS;
    const float* A = attn + (size_t)bh * HD * HD;
    const float* Vb = v + (size_t)b * CC * NN + (size_t)h * HD * NN;
    float*       Ob = o + (size_t)b * CC * NN + (size_t)h * HD * NN;

    __shared__ float As[64 * 64];
    for (int i = threadIdx.x; i < 64 * 64; i += 256) As[i] = A[i];
    __syncthreads();

    float acc[64];
    #pragma unroll
    for (int d = 0; d < 64; d++) acc[d] = 0.f;

    #pragma unroll 4
    for (int e = 0; e < 64; e++) {
        float ve = Vb[(size_t)e * NN + n];
        #pragma unroll
        for (int d = 0; d < 64; d++) acc[d] += As[d * 64 + e] * ve;
    }
    #pragma unroll
    for (int d = 0; d < 64; d++) Ob[(size_t)d * NN + n] = acc[d];
}

// ---------------- launch ----------------
extern "C" void kernel_launch(void* const* d_in, const int* in_sizes, int n_in,
                              void* d_out, int out_size)
{
    const float* x     = (const float*)d_in[0];
    const float* Wq    = (const float*)d_in[1];
    const float* Wk    = (const float*)d_in[2];
    const float* Wv    = (const float*)d_in[3];
    const float* dw_w  = (const float*)d_in[4];
    const float* gamma = (const float*)d_in[5];
    const float* beta  = (const float*)d_in[6];
    const float* temp  = (const float*)d_in[7];
    const float* Wp    = (const float*)d_in[8];
    const float* bp    = (const float*)d_in[9];
    float* out = (float*)d_out;

    float *Qb, *Kb, *Vb, *Gb, *Ob, *Ab;
    cudaGetSymbolAddress((void**)&Qb, g_Q);
    cudaGetSymbolAddress((void**)&Kb, g_K);
    cudaGetSymbolAddress((void**)&Vb, g_V);
    cudaGetSymbolAddress((void**)&Gb, g_G);
    cudaGetSymbolAddress((void**)&Ob, g_O);
    cudaGetSymbolAddress((void**)&Ab, g_attn);

    zero_bn_kernel<<<1, 512>>>();

    dim3 ggrid(NN / 128, CC / 128, BB);   // (8,4,32)
    gemm_mma<<<ggrid, 256>>>(Wq, x, Qb, nullptr);
    gemm_mma<<<ggrid, 256>>>(Wk, x, Kb, nullptr);
    gemm_mma<<<ggrid, 256>>>(Wv, x, Vb, nullptr);

    l2norm_kernel<<<BB * CC, 256>>>(Qb);
    l2norm_kernel<<<BB * CC, 256>>>(Kb);

    attn_kernel<<<BB * HEADS, 256>>>(Qb, Kb, temp, Ab);

    dwconv_kernel<<<BB * CC, 256>>>(x, dw_w, Gb);
    bn_silu_mul_kernel<<<(BB * CC * NN) / 256, 256>>>(Gb, gamma, beta, Vb);

    attn_apply_kernel<<<dim3(BB * HEADS, NN / 256), 256>>>(Ab, Vb, Ob);

    gemm_mma<<<ggrid, 256>>>(Wp, x /*unused placeholder*/ == x ? Ob : Ob, out, bp);
}

// round 4
// speedup vs baseline: 2.4894x; 1.8132x over previous
#include <cuda_runtime.h>
#include <math.h>
#include <stdint.h>

#define BB 32
#define CC 512
#define NN 1024      // H*W = 32*32
#define HEADS 8
#define HD 64
#define BN_EPS 1e-5f

// ---------------- scratch (device globals; no allocation allowed) ----------------
__device__ float g_Q[(size_t)BB * CC * NN];
__device__ float g_K[(size_t)BB * CC * NN];
__device__ float g_V[(size_t)BB * CC * NN];
__device__ float g_G[(size_t)BB * CC * NN];
__device__ float g_O[(size_t)BB * CC * NN];
__device__ float g_XR[(size_t)BB * CC * NN];          // x rounded to tf32
__device__ float g_WR[4 * (size_t)CC * CC];           // Wq,Wk,Wv,Wp rounded
__device__ float g_attn[(size_t)BB * HEADS * HD * HD];
__device__ float g_bnsum[CC];
__device__ float g_bnsum2[CC];
__device__ float g_bnA[CC];                           // gamma*rsqrt(var+eps)
__device__ float g_bnB[CC];                           // beta - mean*A

// ============================ helpers ============================
__device__ __forceinline__ uint32_t smem_u32(const void* p) {
    uint32_t a;
    asm("{ .reg .u64 t; cvta.to.shared.u64 t, %1; cvt.u32.u64 %0, t; }" : "=r"(a) : "l"(p));
    return a;
}
__device__ __forceinline__ void cp_async16(uint32_t dst, const void* src) {
    asm volatile("cp.async.cg.shared.global [%0], [%1], 16;" :: "r"(dst), "l"(src));
}
#define CP_COMMIT() asm volatile("cp.async.commit_group;" ::: "memory")
#define CP_WAIT(n)  asm volatile("cp.async.wait_group %0;" :: "n"(n) : "memory")

__device__ __forceinline__ float to_tf32f(float f) {
    uint32_t r;
    asm("cvt.rna.tf32.f32 %0, %1;" : "=r"(r) : "f"(f));
    return __uint_as_float(r);
}
__device__ __forceinline__ void mma_tf32(float* c, const uint32_t* a, const uint32_t* b) {
    asm volatile("mma.sync.aligned.m16n8k8.row.col.f32.tf32.tf32.f32 "
        "{%0,%1,%2,%3}, {%4,%5,%6,%7}, {%8,%9}, {%0,%1,%2,%3};"
        : "+f"(c[0]), "+f"(c[1]), "+f"(c[2]), "+f"(c[3])
        : "r"(a[0]), "r"(a[1]), "r"(a[2]), "r"(a[3]), "r"(b[0]), "r"(b[1]));
}

// ============================ small kernels ============================
__global__ void zero_bn_kernel() {
    int t = threadIdx.x;
    if (t < CC) { g_bnsum[t] = 0.f; g_bnsum2[t] = 0.f; }
}

__global__ void bn_finalize_kernel(const float* __restrict__ gamma,
                                   const float* __restrict__ beta) {
    int c = threadIdx.x;
    if (c < CC) {
        const float cnt = (float)(BB * NN);
        float mean = g_bnsum[c] / cnt;
        float var  = g_bnsum2[c] / cnt - mean * mean;
        float A = gamma[c] * rsqrtf(var + BN_EPS);
        g_bnA[c] = A;
        g_bnB[c] = beta[c] - mean * A;
    }
}

// round float array to tf32 bit pattern (vectorized)
__global__ __launch_bounds__(256)
void round_tf32_kernel(const float* __restrict__ in, float* __restrict__ out, int n4) {
    int i = blockIdx.x * 256 + threadIdx.x;
    if (i < n4) {
        float4 v = ((const float4*)in)[i];
        v.x = to_tf32f(v.x); v.y = to_tf32f(v.y);
        v.z = to_tf32f(v.z); v.w = to_tf32f(v.w);
        ((float4*)out)[i] = v;
    }
}

// ---- tf32 tensor GEMM: Y[b](512x1024) = W(512x512) @ X[b](512x1024) (+bias) ----
// inputs already tf32-rounded -> no cvt in inner loop
#define BSTRIDE 136
__global__ __launch_bounds__(256)
void gemm_mma(const float* __restrict__ W, const float* __restrict__ X,
              float* __restrict__ Y, const float* __restrict__ bias)
{
    __shared__ float As[2][128 * 16];        // [m][k] float4-level XOR swizzle
    __shared__ float Bs[2][16 * BSTRIDE];    // [k][n] padded

    const int t    = threadIdx.x;
    const int lane = t & 31;
    const int wid  = t >> 5;
    const int wm   = wid & 3;
    const int wn   = wid >> 2;
    const int m0   = blockIdx.y * 128;
    const int n0   = blockIdx.x * 128;
    const int b    = blockIdx.z;

    const float* Ag = W + (size_t)m0 * CC;
    const float* Bg = X + (size_t)b * CC * NN + n0;
    float*       Yb = Y + (size_t)b * CC * NN;

    const uint32_t AsU[2] = { smem_u32(As[0]), smem_u32(As[1]) };
    const uint32_t BsU[2] = { smem_u32(Bs[0]), smem_u32(Bs[1]) };

    float acc[2][8][4];
    #pragma unroll
    for (int i = 0; i < 2; i++)
        #pragma unroll
        for (int j = 0; j < 8; j++)
            #pragma unroll
            for (int q = 0; q < 4; q++) acc[i][j][q] = 0.f;

    auto ld_stage = [&](int s, int k0) {
        #pragma unroll
        for (int i = 0; i < 2; i++) {
            int idx = t + 256 * i;
            int r = idx >> 2, j = idx & 3;
            uint32_t dst = AsU[s] + (uint32_t)(r * 16 + ((j ^ (r & 3)) << 2)) * 4u;
            cp_async16(dst, Ag + (size_t)r * CC + k0 + j * 4);
        }
        #pragma unroll
        for (int i = 0; i < 2; i++) {
            int idx = t + 256 * i;
            int r = idx >> 5, j = idx & 31;
            uint32_t dst = BsU[s] + (uint32_t)(r * BSTRIDE + j * 4) * 4u;
            cp_async16(dst, Bg + (size_t)(k0 + r) * NN + j * 4);
        }
    };

    ld_stage(0, 0);
    CP_COMMIT();

    const int gid = lane >> 2, tig = lane & 3;

    for (int c = 0; c < 32; c++) {
        if (c < 31) { ld_stage((c + 1) & 1, (c + 1) * 16); CP_COMMIT(); CP_WAIT(1); }
        else        { CP_WAIT(0); }
        __syncthreads();

        const uint32_t* Ac = (const uint32_t*)As[c & 1];
        const uint32_t* Bc = (const uint32_t*)Bs[c & 1];

        #pragma unroll
        for (int ks = 0; ks < 2; ks++) {
            uint32_t afr[2][4];
            #pragma unroll
            for (int i = 0; i < 2; i++) {
                int m  = wm * 32 + i * 16 + gid;
                int m8 = m + 8;
                int j0 = ks * 2, j1 = ks * 2 + 1;
                afr[i][0] = Ac[m  * 16 + ((j0 ^ (m  & 3)) << 2) + tig];
                afr[i][1] = Ac[m8 * 16 + ((j0 ^ (m8 & 3)) << 2) + tig];
                afr[i][2] = Ac[m  * 16 + ((j1 ^ (m  & 3)) << 2) + tig];
                afr[i][3] = Ac[m8 * 16 + ((j1 ^ (m8 & 3)) << 2) + tig];
            }
            uint32_t bfr[8][2];
            const int kr = ks * 8 + tig;
            const int nb = wn * 64 + gid;
            #pragma unroll
            for (int j = 0; j < 8; j++) {
                bfr[j][0] = Bc[kr       * BSTRIDE + nb + j * 8];
                bfr[j][1] = Bc[(kr + 4) * BSTRIDE + nb + j * 8];
            }
            #pragma unroll
            for (int i = 0; i < 2; i++)
                #pragma unroll
                for (int j = 0; j < 8; j++)
                    mma_tf32(acc[i][j], afr[i], bfr[j]);
        }
        __syncthreads();
    }

    #pragma unroll
    for (int i = 0; i < 2; i++) {
        int m = m0 + wm * 32 + i * 16 + gid;
        float b0 = bias ? bias[m] : 0.f;
        float b1 = bias ? bias[m + 8] : 0.f;
        float* r0 = Yb + (size_t)m * NN + n0 + wn * 64;
        float* r1 = r0 + 8 * NN;
        #pragma unroll
        for (int j = 0; j < 8; j++) {
            int cb = j * 8 + 2 * tig;
            *(float2*)(r0 + cb) = make_float2(acc[i][j][0] + b0, acc[i][j][1] + b0);
            *(float2*)(r1 + cb) = make_float2(acc[i][j][2] + b1, acc[i][j][3] + b1);
        }
    }
}

// ---- attn = softmax( (Q K^T)/(|q||k|) * temp ) per (b,h), norm fused ----
__global__ __launch_bounds__(256)
void attn_kernel(const float* __restrict__ Q, const float* __restrict__ K,
                 const float* __restrict__ temp, float* __restrict__ attn)
{
    const int bh = blockIdx.x;
    const int b = bh / HEADS, h = bh % HEADS;
    const float* Qb = Q + (size_t)b * CC * NN + (size_t)h * HD * NN;
    const float* Kb = K + (size_t)b * CC * NN + (size_t)h * HD * NN;

    __shared__ float Qs[64][65];
    __shared__ float Ks[64][65];
    __shared__ float inv_q[64], inv_k[64];

    const int t = threadIdx.x;
    const int tx = t % 16, ty = t / 16;

    float acc[4][4];
    #pragma unroll
    for (int i = 0; i < 4; i++)
        #pragma unroll
        for (int j = 0; j < 4; j++) acc[i][j] = 0.f;

    float ss = 0.f;   // per-thread row sumsq (threads 0..127)

    for (int n0 = 0; n0 < NN; n0 += 64) {
        for (int i = t; i < 64 * 64; i += 256) {
            int r = i >> 6, cidx = i & 63;
            Qs[r][cidx] = Qb[(size_t)r * NN + n0 + cidx];
            Ks[r][cidx] = Kb[(size_t)r * NN + n0 + cidx];
        }
        __syncthreads();
        if (t < 64) {
            #pragma unroll 8
            for (int cidx = 0; cidx < 64; cidx++) { float v = Qs[t][cidx]; ss += v * v; }
        } else if (t < 128) {
            #pragma unroll 8
            for (int cidx = 0; cidx < 64; cidx++) { float v = Ks[t - 64][cidx]; ss += v * v; }
        }
        #pragma unroll 8
        for (int nn = 0; nn < 64; nn++) {
            float a[4], bb2[4];
            #pragma unroll
            for (int i = 0; i < 4; i++) a[i] = Qs[ty * 4 + i][nn];
            #pragma unroll
            for (int j = 0; j < 4; j++) bb2[j] = Ks[tx * 4 + j][nn];
            #pragma unroll
            for (int i = 0; i < 4; i++)
                #pragma unroll
                for (int j = 0; j < 4; j++)
                    acc[i][j] += a[i] * bb2[j];
        }
        __syncthreads();
    }

    if (t < 64)       inv_q[t]      = 1.f / fmaxf(sqrtf(ss), 1e-12f);
    else if (t < 128) inv_k[t - 64] = 1.f / fmaxf(sqrtf(ss), 1e-12f);
    __syncthreads();

    float* Ss = &Qs[0][0];          // reuse, row stride 65
    const float tmp = temp[h];
    #pragma unroll
    for (int i = 0; i < 4; i++)
        #pragma unroll
        for (int j = 0; j < 4; j++)
            Ss[(ty * 4 + i) * 65 + (tx * 4 + j)] =
                acc[i][j] * inv_q[ty * 4 + i] * inv_k[tx * 4 + j] * tmp;
    __syncthreads();

    if (t < 64) {
        float mx = -1e30f;
        for (int e = 0; e < 64; e++) mx = fmaxf(mx, Ss[t * 65 + e]);
        float sum = 0.f;
        for (int e = 0; e < 64; e++) {
            float ev = __expf(Ss[t * 65 + e] - mx);
            Ss[t * 65 + e] = ev; sum += ev;
        }
        float inv = 1.f / sum;
        float* out = attn + ((size_t)bh * HD + t) * HD;
        for (int e = 0; e < 64; e++) out[e] = Ss[t * 65 + e] * inv;
    }
}

// ---------------- depthwise 3x3 conv + per-channel sum/sumsq ----------------
__global__ __launch_bounds__(256)
void dwconv_kernel(const float* __restrict__ x, const float* __restrict__ dw,
                   float* __restrict__ g)
{
    const int bc = blockIdx.x;
    const int c = bc % CC;
    const float* img = x + (size_t)bc * NN;

    __shared__ float sm[34][34];
    const int t = threadIdx.x;
    for (int i = t; i < 34 * 34; i += 256) {
        int yy = i / 34 - 1, xx = i % 34 - 1;
        sm[i / 34][i % 34] =
            (yy >= 0 && yy < 32 && xx >= 0 && xx < 32) ? img[yy * 32 + xx] : 0.f;
    }
    float w[9];
    #pragma unroll
    for (int i = 0; i < 9; i++) w[i] = dw[c * 9 + i];
    __syncthreads();

    float s = 0.f, s2 = 0.f;
    for (int p = t; p < NN; p += 256) {
        int y = p >> 5, xx = p & 31;
        float acc = 0.f;
        #pragma unroll
        for (int dy = 0; dy < 3; dy++)
            #pragma unroll
            for (int dx = 0; dx < 3; dx++)
                acc += sm[y + dy][xx + dx] * w[dy * 3 + dx];
        g[(size_t)bc * NN + p] = acc;
        s += acc; s2 += acc * acc;
    }

    __shared__ float r1[256], r2[256];
    r1[t] = s; r2[t] = s2; __syncthreads();
    for (int st = 128; st > 0; st >>= 1) {
        if (t < st) { r1[t] += r1[t + st]; r2[t] += r2[t + st]; }
        __syncthreads();
    }
    if (t == 0) { atomicAdd(&g_bnsum[c], r1[0]); atomicAdd(&g_bnsum2[c], r2[0]); }
}

// ---- O[b,h](64x1024) = attn @ (V * silu(bn(G))), O rounded to tf32 ----
__global__ __launch_bounds__(256)
void attn_apply_kernel(const float* __restrict__ attn, const float* __restrict__ v,
                       const float* __restrict__ gbuf, float* __restrict__ o)
{
    const int bh = blockIdx.x;
    const int n = blockIdx.y * 256 + threadIdx.x;
    const int b = bh / HEADS, h = bh % HEADS;
    const float* A  = attn + (size_t)bh * HD * HD;
    const float* Vb = v    + (size_t)b * CC * NN + (size_t)h * HD * NN;
    const float* Gb = gbuf + (size_t)b * CC * NN + (size_t)h * HD * NN;
    float*       Ob = o    + (size_t)b * CC * NN + (size_t)h * HD * NN;

    __shared__ float As[64 * 64];
    __shared__ float sc[64], sh[64];
    for (int i = threadIdx.x; i < 64 * 64; i += 256) As[i] = A[i];
    if (threadIdx.x < 64) {
        sc[threadIdx.x] = g_bnA[h * 64 + threadIdx.x];
        sh[threadIdx.x] = g_bnB[h * 64 + threadIdx.x];
    }
    __syncthreads();

    float acc[64];
    #pragma unroll
    for (int d = 0; d < 64; d++) acc[d] = 0.f;

    #pragma unroll 4
    for (int e = 0; e < 64; e++) {
        float gv = Gb[(size_t)e * NN + n];
        float gn = gv * sc[e] + sh[e];
        float gate = gn / (1.f + __expf(-gn));
        float ve = Vb[(size_t)e * NN + n] * gate;
        #pragma unroll
        for (int d = 0; d < 64; d++) acc[d] += As[d * 64 + e] * ve;
    }
    #pragma unroll
    for (int d = 0; d < 64; d++) Ob[(size_t)d * NN + n] = to_tf32f(acc[d]);
}

// ---------------- launch ----------------
extern "C" void kernel_launch(void* const* d_in, const int* in_sizes, int n_in,
                              void* d_out, int out_size)
{
    const float* x     = (const float*)d_in[0];
    const float* Wq    = (const float*)d_in[1];
    const float* Wk    = (const float*)d_in[2];
    const float* Wv    = (const float*)d_in[3];
    const float* dw_w  = (const float*)d_in[4];
    const float* gamma = (const float*)d_in[5];
    const float* beta  = (const float*)d_in[6];
    const float* temp  = (const float*)d_in[7];
    const float* Wp    = (const float*)d_in[8];
    const float* bp    = (const float*)d_in[9];
    float* out = (float*)d_out;

    float *Qb, *Kb, *Vb, *Gb, *Ob, *Ab, *XR, *WR;
    cudaGetSymbolAddress((void**)&Qb, g_Q);
    cudaGetSymbolAddress((void**)&Kb, g_K);
    cudaGetSymbolAddress((void**)&Vb, g_V);
    cudaGetSymbolAddress((void**)&Gb, g_G);
    cudaGetSymbolAddress((void**)&Ob, g_O);
    cudaGetSymbolAddress((void**)&Ab, g_attn);
    cudaGetSymbolAddress((void**)&XR, g_XR);
    cudaGetSymbolAddress((void**)&WR, g_WR);

    zero_bn_kernel<<<1, 512>>>();

    // pre-round inputs to tf32 (removes cvt from GEMM inner loop)
    const int nX4 = BB * CC * NN / 4;          // 8,388,608
    const int nW4 = CC * CC / 4;               // 65,536
    round_tf32_kernel<<<(nX4 + 255) / 256, 256>>>(x,  XR, nX4);
    round_tf32_kernel<<<(nW4 + 255) / 256, 256>>>(Wq, WR + 0 * (size_t)CC * CC, nW4);
    round_tf32_kernel<<<(nW4 + 255) / 256, 256>>>(Wk, WR + 1 * (size_t)CC * CC, nW4);
    round_tf32_kernel<<<(nW4 + 255) / 256, 256>>>(Wv, WR + 2 * (size_t)CC * CC, nW4);
    round_tf32_kernel<<<(nW4 + 255) / 256, 256>>>(Wp, WR + 3 * (size_t)CC * CC, nW4);

    dim3 ggrid(NN / 128, CC / 128, BB);   // (8,4,32)
    gemm_mma<<<ggrid, 256>>>(WR + 0 * (size_t)CC * CC, XR, Qb, nullptr);
    gemm_mma<<<ggrid, 256>>>(WR + 1 * (size_t)CC * CC, XR, Kb, nullptr);
    gemm_mma<<<ggrid, 256>>>(WR + 2 * (size_t)CC * CC, XR, Vb, nullptr);

    dwconv_kernel<<<BB * CC, 256>>>(x, dw_w, Gb);
    bn_finalize_kernel<<<1, 512>>>(gamma, beta);

    attn_kernel<<<BB * HEADS, 256>>>(Qb, Kb, temp, Ab);

    attn_apply_kernel<<<dim3(BB * HEADS, NN / 256), 256>>>(Ab, Vb, Gb, Ob);

    gemm_mma<<<ggrid, 256>>>(WR + 3 * (size_t)CC * CC, Ob, out, bp);
}

// round 5
// speedup vs baseline: 3.2575x; 1.3086x over previous
#include <cuda_runtime.h>
#include <cuda_fp16.h>
#include <math.h>
#include <stdint.h>

#define BB 32
#define CC 512
#define NN 1024      // H*W = 32*32
#define HEADS 8
#define HD 64
#define BN_EPS 1e-5f
#define BCN ((size_t)BB * CC * NN)

// ---------------- scratch (device globals; no allocation allowed) ----------------
__device__ float  g_QKV[3 * BCN];                 // Q,K,V fp32
__device__ float  g_G[BCN];                       // dwconv output
__device__ __half g_Oh[BCN];                      // attention output (half)
__device__ __half g_Xh[BCN];                      // x in half
__device__ __half g_Wh[3 * (size_t)CC * CC];      // Wq,Wk,Wv stacked half
__device__ __half g_Wph[(size_t)CC * CC];         // Wp half
__device__ float  g_attn[(size_t)BB * HEADS * HD * HD];
__device__ float  g_bnsum[CC];
__device__ float  g_bnsum2[CC];
__device__ float  g_bnA[CC];
__device__ float  g_bnB[CC];

// ============================ helpers ============================
__device__ __forceinline__ uint32_t smem_u32(const void* p) {
    uint32_t a;
    asm("{ .reg .u64 t; cvta.to.shared.u64 t, %1; cvt.u32.u64 %0, t; }" : "=r"(a) : "l"(p));
    return a;
}
__device__ __forceinline__ void cp_async16(uint32_t dst, const void* src) {
    asm volatile("cp.async.cg.shared.global [%0], [%1], 16;" :: "r"(dst), "l"(src));
}
#define CP_COMMIT() asm volatile("cp.async.commit_group;" ::: "memory")
#define CP_WAIT(n)  asm volatile("cp.async.wait_group %0;" :: "n"(n) : "memory")

__device__ __forceinline__ void ldsm4(uint32_t* r, uint32_t addr) {
    asm volatile("ldmatrix.sync.aligned.m8n8.x4.shared.b16 {%0,%1,%2,%3}, [%4];"
        : "=r"(r[0]), "=r"(r[1]), "=r"(r[2]), "=r"(r[3]) : "r"(addr));
}
__device__ __forceinline__ void ldsm4t(uint32_t* r, uint32_t addr) {
    asm volatile("ldmatrix.sync.aligned.m8n8.x4.trans.shared.b16 {%0,%1,%2,%3}, [%4];"
        : "=r"(r[0]), "=r"(r[1]), "=r"(r[2]), "=r"(r[3]) : "r"(addr));
}
__device__ __forceinline__ void mma_f16(float* c, const uint32_t* a, const uint32_t* b) {
    asm volatile("mma.sync.aligned.m16n8k16.row.col.f32.f16.f16.f32 "
        "{%0,%1,%2,%3}, {%4,%5,%6,%7}, {%8,%9}, {%0,%1,%2,%3};"
        : "+f"(c[0]), "+f"(c[1]), "+f"(c[2]), "+f"(c[3])
        : "r"(a[0]), "r"(a[1]), "r"(a[2]), "r"(a[3]), "r"(b[0]), "r"(b[1]));
}

// ============================ small kernels ============================
__global__ void zero_bn_kernel() {
    int t = threadIdx.x;
    if (t < CC) { g_bnsum[t] = 0.f; g_bnsum2[t] = 0.f; }
}

__global__ void bn_finalize_kernel(const float* __restrict__ gamma,
                                   const float* __restrict__ beta) {
    int c = threadIdx.x;
    if (c < CC) {
        const float cnt = (float)(BB * NN);
        float mean = g_bnsum[c] / cnt;
        float var  = g_bnsum2[c] / cnt - mean * mean;
        float A = gamma[c] * rsqrtf(var + BN_EPS);
        g_bnA[c] = A;
        g_bnB[c] = beta[c] - mean * A;
    }
}

// float -> half, 4 at a time
__global__ __launch_bounds__(256)
void f2h_kernel(const float* __restrict__ in, __half* __restrict__ out, int n4) {
    int i = blockIdx.x * 256 + threadIdx.x;
    if (i < n4) {
        float4 v = ((const float4*)in)[i];
        __half2* o = (__half2*)out;
        o[2 * i]     = __floats2half2_rn(v.x, v.y);
        o[2 * i + 1] = __floats2half2_rn(v.z, v.w);
    }
}

// ---- fp16 tensor GEMM: Y[mat][b](512x1024) = A(m x 512,half) @ Bh[b](512x1024,half) ----
// tile 128x128, BK=32, 256 threads (8 warps, 4(M)x2(N)), warp tile 32x64
// A smem rows padded to 40 halves (80B), B rows to 136 halves (272B): ldmatrix conflict-free
#define ASTRH 40
#define BSTRH 136
__global__ __launch_bounds__(256)
void gemm_h(const __half* __restrict__ A, const __half* __restrict__ Bh,
            float* __restrict__ Y, const float* __restrict__ bias)
{
    __shared__ __half As[2][128 * ASTRH];
    __shared__ __half Bs[2][32 * BSTRH];

    const int t    = threadIdx.x;
    const int lane = t & 31;
    const int wid  = t >> 5;
    const int wm   = wid & 3;
    const int wn   = wid >> 2;
    const int m0g  = blockIdx.y * 128;            // global row in stacked A
    const int mat  = m0g >> 9;                    // which output matrix (0..2 for QKV)
    const int mrow0 = m0g & 511;
    const int n0   = blockIdx.x * 128;
    const int b    = blockIdx.z;

    const __half* Ag = A + (size_t)m0g * CC;
    const __half* Bg = Bh + (size_t)b * CC * NN + n0;
    float*        Yb = Y + (size_t)mat * BCN + (size_t)b * CC * NN;

    const uint32_t AsU[2] = { smem_u32(As[0]), smem_u32(As[1]) };
    const uint32_t BsU[2] = { smem_u32(Bs[0]), smem_u32(Bs[1]) };

    float acc[2][8][4];
    #pragma unroll
    for (int i = 0; i < 2; i++)
        #pragma unroll
        for (int j = 0; j < 8; j++)
            #pragma unroll
            for (int q = 0; q < 4; q++) acc[i][j][q] = 0.f;

    // per stage: A 128x32 halves (512 chunks of 8 halves), B 32x128 halves (512 chunks)
    auto ld_stage = [&](int s, int k0) {
        #pragma unroll
        for (int i = 0; i < 2; i++) {
            int idx = t + 256 * i;
            int r = idx >> 2, j = idx & 3;
            cp_async16(AsU[s] + (uint32_t)(r * ASTRH + j * 8) * 2u,
                       Ag + (size_t)r * CC + k0 + j * 8);
        }
        #pragma unroll
        for (int i = 0; i < 2; i++) {
            int idx = t + 256 * i;
            int r = idx >> 4, j = idx & 15;
            cp_async16(BsU[s] + (uint32_t)(r * BSTRH + j * 8) * 2u,
                       Bg + (size_t)(k0 + r) * NN + j * 8);
        }
    };

    ld_stage(0, 0);
    CP_COMMIT();

    const int gid = lane >> 2, tig = lane & 3;
    const int arow = lane & 15, achk = lane >> 4;   // ldmatrix addressing

    for (int c = 0; c < 16; c++) {
        if (c < 15) { ld_stage((c + 1) & 1, (c + 1) * 32); CP_COMMIT(); CP_WAIT(1); }
        else        { CP_WAIT(0); }
        __syncthreads();

        const uint32_t Au = AsU[c & 1];
        const uint32_t Bu = BsU[c & 1];

        #pragma unroll
        for (int ks = 0; ks < 2; ks++) {
            uint32_t ra[2][4];
            #pragma unroll
            for (int mi = 0; mi < 2; mi++) {
                int row = wm * 32 + mi * 16 + arow;
                ldsm4(ra[mi], Au + (uint32_t)(row * ASTRH + ks * 16 + achk * 8) * 2u);
            }
            uint32_t rb[4][4];
            #pragma unroll
            for (int nb = 0; nb < 4; nb++) {
                int krow = ks * 16 + arow;
                int col  = wn * 64 + nb * 16 + achk * 8;
                ldsm4t(rb[nb], Bu + (uint32_t)(krow * BSTRH + col) * 2u);
            }
            #pragma unroll
            for (int mi = 0; mi < 2; mi++)
                #pragma unroll
                for (int j = 0; j < 8; j++)
                    mma_f16(acc[mi][j], ra[mi], &rb[j >> 1][(j & 1) * 2]);
        }
        __syncthreads();
    }

    #pragma unroll
    for (int i = 0; i < 2; i++) {
        int ml = mrow0 + wm * 32 + i * 16 + gid;
        float b0 = bias ? bias[ml] : 0.f;
        float b1 = bias ? bias[ml + 8] : 0.f;
        float* r0 = Yb + (size_t)ml * NN + n0 + wn * 64;
        float* r1 = r0 + 8 * NN;
        #pragma unroll
        for (int j = 0; j < 8; j++) {
            int cb = j * 8 + 2 * tig;
            *(float2*)(r0 + cb) = make_float2(acc[i][j][0] + b0, acc[i][j][1] + b0);
            *(float2*)(r1 + cb) = make_float2(acc[i][j][2] + b1, acc[i][j][3] + b1);
        }
    }
}

// ---- attn = softmax( (Q K^T)/(|q||k|) * temp ) per (b,h), norm fused ----
__global__ __launch_bounds__(256)
void attn_kernel(const float* __restrict__ Q, const float* __restrict__ K,
                 const float* __restrict__ temp, float* __restrict__ attn)
{
    const int bh = blockIdx.x;
    const int b = bh / HEADS, h = bh % HEADS;
    const float* Qb = Q + (size_t)b * CC * NN + (size_t)h * HD * NN;
    const float* Kb = K + (size_t)b * CC * NN + (size_t)h * HD * NN;

    __shared__ float Qs[64][65];
    __shared__ float Ks[64][65];
    __shared__ float inv_q[64], inv_k[64];

    const int t = threadIdx.x;
    const int tx = t % 16, ty = t / 16;

    float acc[4][4];
    #pragma unroll
    for (int i = 0; i < 4; i++)
        #pragma unroll
        for (int j = 0; j < 4; j++) acc[i][j] = 0.f;

    float ss = 0.f;

    for (int n0 = 0; n0 < NN; n0 += 64) {
        for (int i = t; i < 64 * 64; i += 256) {
            int r = i >> 6, cidx = i & 63;
            Qs[r][cidx] = Qb[(size_t)r * NN + n0 + cidx];
            Ks[r][cidx] = Kb[(size_t)r * NN + n0 + cidx];
        }
        __syncthreads();
        if (t < 64) {
            #pragma unroll 8
            for (int cidx = 0; cidx < 64; cidx++) { float v = Qs[t][cidx]; ss += v * v; }
        } else if (t < 128) {
            #pragma unroll 8
            for (int cidx = 0; cidx < 64; cidx++) { float v = Ks[t - 64][cidx]; ss += v * v; }
        }
        #pragma unroll 8
        for (int nn = 0; nn < 64; nn++) {
            float a[4], bb2[4];
            #pragma unroll
            for (int i = 0; i < 4; i++) a[i] = Qs[ty * 4 + i][nn];
            #pragma unroll
            for (int j = 0; j < 4; j++) bb2[j] = Ks[tx * 4 + j][nn];
            #pragma unroll
            for (int i = 0; i < 4; i++)
                #pragma unroll
                for (int j = 0; j < 4; j++)
                    acc[i][j] += a[i] * bb2[j];
        }
        __syncthreads();
    }

    if (t < 64)       inv_q[t]      = 1.f / fmaxf(sqrtf(ss), 1e-12f);
    else if (t < 128) inv_k[t - 64] = 1.f / fmaxf(sqrtf(ss), 1e-12f);
    __syncthreads();

    float* Ss = &Qs[0][0];
    const float tmp = temp[h];
    #pragma unroll
    for (int i = 0; i < 4; i++)
        #pragma unroll
        for (int j = 0; j < 4; j++)
            Ss[(ty * 4 + i) * 65 + (tx * 4 + j)] =
                acc[i][j] * inv_q[ty * 4 + i] * inv_k[tx * 4 + j] * tmp;
    __syncthreads();

    if (t < 64) {
        float mx = -1e30f;
        for (int e = 0; e < 64; e++) mx = fmaxf(mx, Ss[t * 65 + e]);
        float sum = 0.f;
        for (int e = 0; e < 64; e++) {
            float ev = __expf(Ss[t * 65 + e] - mx);
            Ss[t * 65 + e] = ev; sum += ev;
        }
        float inv = 1.f / sum;
        float* out = attn + ((size_t)bh * HD + t) * HD;
        for (int e = 0; e < 64; e++) out[e] = Ss[t * 65 + e] * inv;
    }
}

// ---------------- depthwise 3x3 conv + per-channel sum/sumsq ----------------
__global__ __launch_bounds__(256)
void dwconv_kernel(const float* __restrict__ x, const float* __restrict__ dw,
                   float* __restrict__ g)
{
    const int bc = blockIdx.x;
    const int c = bc % CC;
    const float* img = x + (size_t)bc * NN;

    __shared__ float sm[34][34];
    const int t = threadIdx.x;
    for (int i = t; i < 34 * 34; i += 256) {
        int yy = i / 34 - 1, xx = i % 34 - 1;
        sm[i / 34][i % 34] =
            (yy >= 0 && yy < 32 && xx >= 0 && xx < 32) ? img[yy * 32 + xx] : 0.f;
    }
    float w[9];
    #pragma unroll
    for (int i = 0; i < 9; i++) w[i] = dw[c * 9 + i];
    __syncthreads();

    float s = 0.f, s2 = 0.f;
    for (int p = t; p < NN; p += 256) {
        int y = p >> 5, xx = p & 31;
        float acc = 0.f;
        #pragma unroll
        for (int dy = 0; dy < 3; dy++)
            #pragma unroll
            for (int dx = 0; dx < 3; dx++)
                acc += sm[y + dy][xx + dx] * w[dy * 3 + dx];
        g[(size_t)bc * NN + p] = acc;
        s += acc; s2 += acc * acc;
    }

    __shared__ float r1[256], r2[256];
    r1[t] = s; r2[t] = s2; __syncthreads();
    for (int st = 128; st > 0; st >>= 1) {
        if (t < st) { r1[t] += r1[t + st]; r2[t] += r2[t + st]; }
        __syncthreads();
    }
    if (t == 0) { atomicAdd(&g_bnsum[c], r1[0]); atomicAdd(&g_bnsum2[c], r2[0]); }
}

// ---- O[b,h](64x1024) = attn @ (V * silu(bn(G))), O written as half ----
__global__ __launch_bounds__(256)
void attn_apply_kernel(const float* __restrict__ attn, const float* __restrict__ v,
                       const float* __restrict__ gbuf, __half* __restrict__ o)
{
    const int bh = blockIdx.x;
    const int n = blockIdx.y * 256 + threadIdx.x;
    const int b = bh / HEADS, h = bh % HEADS;
    const float* A  = attn + (size_t)bh * HD * HD;
    const float* Vb = v    + (size_t)b * CC * NN + (size_t)h * HD * NN;
    const float* Gb = gbuf + (size_t)b * CC * NN + (size_t)h * HD * NN;
    __half*      Ob = o    + (size_t)b * CC * NN + (size_t)h * HD * NN;

    __shared__ float As[64 * 64];
    __shared__ float sc[64], sh[64];
    for (int i = threadIdx.x; i < 64 * 64; i += 256) As[i] = A[i];
    if (threadIdx.x < 64) {
        sc[threadIdx.x] = g_bnA[h * 64 + threadIdx.x];
        sh[threadIdx.x] = g_bnB[h * 64 + threadIdx.x];
    }
    __syncthreads();

    float acc[64];
    #pragma unroll
    for (int d = 0; d < 64; d++) acc[d] = 0.f;

    #pragma unroll 4
    for (int e = 0; e < 64; e++) {
        float gv = Gb[(size_t)e * NN + n];
        float gn = gv * sc[e] + sh[e];
        float gate = gn / (1.f + __expf(-gn));
        float ve = Vb[(size_t)e * NN + n] * gate;
        #pragma unroll
        for (int d = 0; d < 64; d++) acc[d] += As[d * 64 + e] * ve;
    }
    #pragma unroll
    for (int d = 0; d < 64; d++) Ob[(size_t)d * NN + n] = __float2half_rn(acc[d]);
}

// ---------------- launch ----------------
extern "C" void kernel_launch(void* const* d_in, const int* in_sizes, int n_in,
                              void* d_out, int out_size)
{
    const float* x     = (const float*)d_in[0];
    const float* Wq    = (const float*)d_in[1];
    const float* Wk    = (const float*)d_in[2];
    const float* Wv    = (const float*)d_in[3];
    const float* dw_w  = (const float*)d_in[4];
    const float* gamma = (const float*)d_in[5];
    const float* beta  = (const float*)d_in[6];
    const float* temp  = (const float*)d_in[7];
    const float* Wp    = (const float*)d_in[8];
    const float* bp    = (const float*)d_in[9];
    float* out = (float*)d_out;

    float *QKV, *Gb, *Ab;
    __half *Xh, *Wh, *Wph, *Oh;
    cudaGetSymbolAddress((void**)&QKV, g_QKV);
    cudaGetSymbolAddress((void**)&Gb,  g_G);
    cudaGetSymbolAddress((void**)&Ab,  g_attn);
    cudaGetSymbolAddress((void**)&Xh,  g_Xh);
    cudaGetSymbolAddress((void**)&Wh,  g_Wh);
    cudaGetSymbolAddress((void**)&Wph, g_Wph);
    cudaGetSymbolAddress((void**)&Oh,  g_Oh);

    zero_bn_kernel<<<1, 512>>>();

    const int nX4 = BB * CC * NN / 4;
    const int nW4 = CC * CC / 4;
    f2h_kernel<<<(nX4 + 255) / 256, 256>>>(x,  Xh, nX4);
    f2h_kernel<<<(nW4 + 255) / 256, 256>>>(Wq, Wh + 0 * (size_t)CC * CC, nW4);
    f2h_kernel<<<(nW4 + 255) / 256, 256>>>(Wk, Wh + 1 * (size_t)CC * CC, nW4);
    f2h_kernel<<<(nW4 + 255) / 256, 256>>>(Wv, Wh + 2 * (size_t)CC * CC, nW4);
    f2h_kernel<<<(nW4 + 255) / 256, 256>>>(Wp, Wph, nW4);

    // fused QKV GEMM: stacked A (1536x512)
    gemm_h<<<dim3(NN / 128, 3 * CC / 128, BB), 256>>>(Wh, Xh, QKV, nullptr);

    dwconv_kernel<<<BB * CC, 256>>>(x, dw_w, Gb);
    bn_finalize_kernel<<<1, 512>>>(gamma, beta);

    attn_kernel<<<BB * HEADS, 256>>>(QKV, QKV + BCN, temp, Ab);

    attn_apply_kernel<<<dim3(BB * HEADS, NN / 256), 256>>>(Ab, QKV + 2 * BCN, Gb, Oh);

    gemm_h<<<dim3(NN / 128, CC / 128, BB), 256>>>(Wph, Oh, out, bp);
}

// round 6
// speedup vs baseline: 3.4531x; 1.0600x over previous
#include <cuda_runtime.h>
#include <cuda_fp16.h>
#include <math.h>
#include <stdint.h>

#define BB 32
#define CC 512
#define NN 1024      // H*W = 32*32
#define HEADS 8
#define HD 64
#define BN_EPS 1e-5f
#define BCN ((size_t)BB * CC * NN)

// ---------------- scratch (device globals; no allocation allowed) ----------------
__device__ __half g_QKVh[3 * BCN];                // Q,K,V half
__device__ __half g_Gh[BCN];                      // dwconv output half
__device__ __half g_Oh[BCN];                      // attention output half
__device__ __half g_Xh[BCN];                      // x in half
__device__ __half g_Wh[3 * (size_t)CC * CC];      // Wq,Wk,Wv stacked half
__device__ __half g_Wph[(size_t)CC * CC];         // Wp half
__device__ float  g_attn[(size_t)BB * HEADS * HD * HD];
__device__ float  g_bnsum[CC];
__device__ float  g_bnsum2[CC];
__device__ float  g_bnA[CC];
__device__ float  g_bnB[CC];

// ============================ helpers ============================
__device__ __forceinline__ uint32_t smem_u32(const void* p) {
    uint32_t a;
    asm("{ .reg .u64 t; cvta.to.shared.u64 t, %1; cvt.u32.u64 %0, t; }" : "=r"(a) : "l"(p));
    return a;
}
__device__ __forceinline__ void cp_async16(uint32_t dst, const void* src) {
    asm volatile("cp.async.cg.shared.global [%0], [%1], 16;" :: "r"(dst), "l"(src));
}
#define CP_COMMIT() asm volatile("cp.async.commit_group;" ::: "memory")
#define CP_WAIT(n)  asm volatile("cp.async.wait_group %0;" :: "n"(n) : "memory")

__device__ __forceinline__ void ldsm4(uint32_t* r, uint32_t addr) {
    asm volatile("ldmatrix.sync.aligned.m8n8.x4.shared.b16 {%0,%1,%2,%3}, [%4];"
        : "=r"(r[0]), "=r"(r[1]), "=r"(r[2]), "=r"(r[3]) : "r"(addr));
}
__device__ __forceinline__ void ldsm4t(uint32_t* r, uint32_t addr) {
    asm volatile("ldmatrix.sync.aligned.m8n8.x4.trans.shared.b16 {%0,%1,%2,%3}, [%4];"
        : "=r"(r[0]), "=r"(r[1]), "=r"(r[2]), "=r"(r[3]) : "r"(addr));
}
__device__ __forceinline__ void mma_f16(float* c, const uint32_t* a, const uint32_t* b) {
    asm volatile("mma.sync.aligned.m16n8k16.row.col.f32.f16.f16.f32 "
        "{%0,%1,%2,%3}, {%4,%5,%6,%7}, {%8,%9}, {%0,%1,%2,%3};"
        : "+f"(c[0]), "+f"(c[1]), "+f"(c[2]), "+f"(c[3])
        : "r"(a[0]), "r"(a[1]), "r"(a[2]), "r"(a[3]), "r"(b[0]), "r"(b[1]));
}

// ============================ small kernels ============================
__global__ void zero_bn_kernel() {
    int t = threadIdx.x;
    if (t < CC) { g_bnsum[t] = 0.f; g_bnsum2[t] = 0.f; }
}

__global__ void bn_finalize_kernel(const float* __restrict__ gamma,
                                   const float* __restrict__ beta) {
    int c = threadIdx.x;
    if (c < CC) {
        const float cnt = (float)(BB * NN);
        float mean = g_bnsum[c] / cnt;
        float var  = g_bnsum2[c] / cnt - mean * mean;
        float A = gamma[c] * rsqrtf(var + BN_EPS);
        g_bnA[c] = A;
        g_bnB[c] = beta[c] - mean * A;
    }
}

__global__ __launch_bounds__(256)
void f2h_kernel(const float* __restrict__ in, __half* __restrict__ out, int n4) {
    int i = blockIdx.x * 256 + threadIdx.x;
    if (i < n4) {
        float4 v = ((const float4*)in)[i];
        __half2* o = (__half2*)out;
        o[2 * i]     = __floats2half2_rn(v.x, v.y);
        o[2 * i + 1] = __floats2half2_rn(v.z, v.w);
    }
}

// ---- fp16 tensor GEMM, templated output type ----
#define ASTRH 40
#define BSTRH 136
template <typename OT>
__global__ __launch_bounds__(256)
void gemm_h(const __half* __restrict__ A, const __half* __restrict__ Bh,
            OT* __restrict__ Y, const float* __restrict__ bias)
{
    __shared__ __half As[2][128 * ASTRH];
    __shared__ __half Bs[2][32 * BSTRH];

    const int t    = threadIdx.x;
    const int lane = t & 31;
    const int wid  = t >> 5;
    const int wm   = wid & 3;
    const int wn   = wid >> 2;
    const int m0g  = blockIdx.y * 128;
    const int mat  = m0g >> 9;
    const int mrow0 = m0g & 511;
    const int n0   = blockIdx.x * 128;
    const int b    = blockIdx.z;

    const __half* Ag = A + (size_t)m0g * CC;
    const __half* Bg = Bh + (size_t)b * CC * NN + n0;
    OT*           Yb = Y + (size_t)mat * BCN + (size_t)b * CC * NN;

    const uint32_t AsU[2] = { smem_u32(As[0]), smem_u32(As[1]) };
    const uint32_t BsU[2] = { smem_u32(Bs[0]), smem_u32(Bs[1]) };

    float acc[2][8][4];
    #pragma unroll
    for (int i = 0; i < 2; i++)
        #pragma unroll
        for (int j = 0; j < 8; j++)
            #pragma unroll
            for (int q = 0; q < 4; q++) acc[i][j][q] = 0.f;

    auto ld_stage = [&](int s, int k0) {
        #pragma unroll
        for (int i = 0; i < 2; i++) {
            int idx = t + 256 * i;
            int r = idx >> 2, j = idx & 3;
            cp_async16(AsU[s] + (uint32_t)(r * ASTRH + j * 8) * 2u,
                       Ag + (size_t)r * CC + k0 + j * 8);
        }
        #pragma unroll
        for (int i = 0; i < 2; i++) {
            int idx = t + 256 * i;
            int r = idx >> 4, j = idx & 15;
            cp_async16(BsU[s] + (uint32_t)(r * BSTRH + j * 8) * 2u,
                       Bg + (size_t)(k0 + r) * NN + j * 8);
        }
    };

    ld_stage(0, 0);
    CP_COMMIT();

    const int gid = lane >> 2, tig = lane & 3;
    const int arow = lane & 15, achk = lane >> 4;

    for (int c = 0; c < 16; c++) {
        if (c < 15) { ld_stage((c + 1) & 1, (c + 1) * 32); CP_COMMIT(); CP_WAIT(1); }
        else        { CP_WAIT(0); }
        __syncthreads();

        const uint32_t Au = AsU[c & 1];
        const uint32_t Bu = BsU[c & 1];

        #pragma unroll
        for (int ks = 0; ks < 2; ks++) {
            uint32_t ra[2][4];
            #pragma unroll
            for (int mi = 0; mi < 2; mi++) {
                int row = wm * 32 + mi * 16 + arow;
                ldsm4(ra[mi], Au + (uint32_t)(row * ASTRH + ks * 16 + achk * 8) * 2u);
            }
            uint32_t rb[4][4];
            #pragma unroll
            for (int nb = 0; nb < 4; nb++) {
                int krow = ks * 16 + arow;
                int col  = wn * 64 + nb * 16 + achk * 8;
                ldsm4t(rb[nb], Bu + (uint32_t)(krow * BSTRH + col) * 2u);
            }
            #pragma unroll
            for (int mi = 0; mi < 2; mi++)
                #pragma unroll
                for (int j = 0; j < 8; j++)
                    mma_f16(acc[mi][j], ra[mi], &rb[j >> 1][(j & 1) * 2]);
        }
        __syncthreads();
    }

    #pragma unroll
    for (int i = 0; i < 2; i++) {
        int ml = mrow0 + wm * 32 + i * 16 + gid;
        float b0 = bias ? bias[ml] : 0.f;
        float b1 = bias ? bias[ml + 8] : 0.f;
        OT* r0 = Yb + (size_t)ml * NN + n0 + wn * 64;
        OT* r1 = r0 + 8 * NN;
        #pragma unroll
        for (int j = 0; j < 8; j++) {
            int cb = j * 8 + 2 * tig;
            if constexpr (sizeof(OT) == 4) {
                *(float2*)((float*)r0 + cb) = make_float2(acc[i][j][0] + b0, acc[i][j][1] + b0);
                *(float2*)((float*)r1 + cb) = make_float2(acc[i][j][2] + b1, acc[i][j][3] + b1);
            } else {
                *(__half2*)((__half*)r0 + cb) = __floats2half2_rn(acc[i][j][0] + b0, acc[i][j][1] + b0);
                *(__half2*)((__half*)r1 + cb) = __floats2half2_rn(acc[i][j][2] + b1, acc[i][j][3] + b1);
            }
        }
    }
}

// ---- attn = softmax( (Q K^T)/(|q||k|) * temp ) per (b,h), tensor-core gram ----
#define QSTR 72   // halves per row; 144B stride -> ldmatrix conflict-free
__global__ __launch_bounds__(128)
void attn_kernel(const __half* __restrict__ Q, const __half* __restrict__ K,
                 const float* __restrict__ temp, float* __restrict__ attn)
{
    const int bh = blockIdx.x;
    const int b = bh / HEADS, h = bh % HEADS;
    const __half* Qb = Q + (size_t)b * CC * NN + (size_t)h * HD * NN;
    const __half* Kb = K + (size_t)b * CC * NN + (size_t)h * HD * NN;

    __shared__ __half Qs[64 * QSTR];
    __shared__ __half Ks[64 * QSTR];
    __shared__ float Ss[64 * 65];
    __shared__ float ssq[64], ssk[64], inv_q[64], inv_k[64];

    const int t = threadIdx.x;
    const int lane = t & 31;
    const int wid = t >> 5;           // 0..3
    const int wm = wid >> 1, wn = wid & 1;

    if (t < 64) { ssq[t] = 0.f; ssk[t] = 0.f; }
    __syncthreads();

    const uint32_t QsU = smem_u32(Qs), KsU = smem_u32(Ks);

    float acc[2][4][4];
    #pragma unroll
    for (int mi = 0; mi < 2; mi++)
        #pragma unroll
        for (int j = 0; j < 4; j++)
            #pragma unroll
            for (int q = 0; q < 4; q++) acc[mi][j][q] = 0.f;

    for (int ch = 0; ch < 16; ch++) {
        const int n0 = ch * 64;
        #pragma unroll
        for (int i = 0; i < 4; i++) {
            int c = t + 128 * i;
            int r = c >> 3, j = c & 7;
            uint4 v = *(const uint4*)(Qb + (size_t)r * NN + n0 + j * 8);
            *(uint4*)&Qs[r * QSTR + j * 8] = v;
            const __half2* hp = (const __half2*)&v;
            float s = 0.f;
            #pragma unroll
            for (int q = 0; q < 4; q++) { float2 f = __half22float2(hp[q]); s += f.x * f.x + f.y * f.y; }
            atomicAdd(&ssq[r], s);
            uint4 w = *(const uint4*)(Kb + (size_t)r * NN + n0 + j * 8);
            *(uint4*)&Ks[r * QSTR + j * 8] = w;
            const __half2* hq = (const __half2*)&w;
            float s2 = 0.f;
            #pragma unroll
            for (int q = 0; q < 4; q++) { float2 f = __half22float2(hq[q]); s2 += f.x * f.x + f.y * f.y; }
            atomicAdd(&ssk[r], s2);
        }
        __syncthreads();

        #pragma unroll
        for (int ks = 0; ks < 4; ks++) {
            uint32_t ra[2][4], rb[2][4];
            #pragma unroll
            for (int mi = 0; mi < 2; mi++)
                ldsm4(ra[mi], QsU + (uint32_t)((wm * 32 + mi * 16 + (lane & 15)) * QSTR
                                               + ks * 16 + (lane >> 4) * 8) * 2u);
            #pragma unroll
            for (int nb = 0; nb < 2; nb++)
                ldsm4(rb[nb], KsU + (uint32_t)((wn * 32 + nb * 16 + (lane & 15)) * QSTR
                                               + ks * 16 + (lane >> 4) * 8) * 2u);
            #pragma unroll
            for (int mi = 0; mi < 2; mi++)
                #pragma unroll
                for (int j = 0; j < 4; j++) {
                    uint32_t bb[2] = { rb[j >> 1][j & 1], rb[j >> 1][(j & 1) + 2] };
                    mma_f16(acc[mi][j], ra[mi], bb);
                }
        }
        __syncthreads();
    }

    if (t < 64) {
        inv_q[t] = 1.f / fmaxf(sqrtf(ssq[t]), 1e-12f);
        inv_k[t] = 1.f / fmaxf(sqrtf(ssk[t]), 1e-12f);
    }
    __syncthreads();

    const float tmp = temp[h];
    const int gid = lane >> 2, tig = lane & 3;
    #pragma unroll
    for (int mi = 0; mi < 2; mi++)
        #pragma unroll
        for (int j = 0; j < 4; j++)
            #pragma unroll
            for (int q = 0; q < 4; q++) {
                int m = wm * 32 + mi * 16 + gid + ((q >> 1) << 3);
                int n = wn * 32 + j * 8 + 2 * tig + (q & 1);
                Ss[m * 65 + n] = acc[mi][j][q] * inv_q[m] * inv_k[n] * tmp;
            }
    __syncthreads();

    if (t < 64) {
        float mx = -1e30f;
        #pragma unroll 8
        for (int e = 0; e < 64; e++) mx = fmaxf(mx, Ss[t * 65 + e]);
        float sum = 0.f;
        #pragma unroll 8
        for (int e = 0; e < 64; e++) {
            float ev = __expf(Ss[t * 65 + e] - mx);
            Ss[t * 65 + e] = ev; sum += ev;
        }
        float inv = 1.f / sum;
        float* out = attn + ((size_t)bh * HD + t) * HD;
        #pragma unroll 8
        for (int e = 0; e < 64; e++) out[e] = Ss[t * 65 + e] * inv;
    }
}

// ---------------- depthwise 3x3 conv (half out) + per-channel sum/sumsq ----------------
__global__ __launch_bounds__(256)
void dwconv_kernel(const float* __restrict__ x, const float* __restrict__ dw,
                   __half* __restrict__ g)
{
    const int bc = blockIdx.x;
    const int c = bc % CC;
    const float* img = x + (size_t)bc * NN;

    __shared__ float sm[34][34];
    const int t = threadIdx.x;
    for (int i = t; i < 34 * 34; i += 256) {
        int yy = i / 34 - 1, xx = i % 34 - 1;
        sm[i / 34][i % 34] =
            (yy >= 0 && yy < 32 && xx >= 0 && xx < 32) ? img[yy * 32 + xx] : 0.f;
    }
    float w[9];
    #pragma unroll
    for (int i = 0; i < 9; i++) w[i] = dw[c * 9 + i];
    __syncthreads();

    float s = 0.f, s2 = 0.f;
    for (int p = t; p < NN; p += 256) {
        int y = p >> 5, xx = p & 31;
        float acc = 0.f;
        #pragma unroll
        for (int dy = 0; dy < 3; dy++)
            #pragma unroll
            for (int dx = 0; dx < 3; dx++)
                acc += sm[y + dy][xx + dx] * w[dy * 3 + dx];
        g[(size_t)bc * NN + p] = __float2half_rn(acc);
        s += acc; s2 += acc * acc;
    }

    __shared__ float r1[256], r2[256];
    r1[t] = s; r2[t] = s2; __syncthreads();
    for (int st = 128; st > 0; st >>= 1) {
        if (t < st) { r1[t] += r1[t + st]; r2[t] += r2[t + st]; }
        __syncthreads();
    }
    if (t == 0) { atomicAdd(&g_bnsum[c], r1[0]); atomicAdd(&g_bnsum2[c], r2[0]); }
}

// ---- O[b,h](64x1024) = attn @ (V * silu(bn(G))), half in/out ----
__global__ __launch_bounds__(256)
void attn_apply_kernel(const float* __restrict__ attn, const __half* __restrict__ v,
                       const __half* __restrict__ gbuf, __half* __restrict__ o)
{
    const int bh = blockIdx.x;
    const int n = blockIdx.y * 256 + threadIdx.x;
    const int b = bh / HEADS, h = bh % HEADS;
    const float*  A  = attn + (size_t)bh * HD * HD;
    const __half* Vb = v    + (size_t)b * CC * NN + (size_t)h * HD * NN;
    const __half* Gb = gbuf + (size_t)b * CC * NN + (size_t)h * HD * NN;
    __half*       Ob = o    + (size_t)b * CC * NN + (size_t)h * HD * NN;

    __shared__ float As[64 * 64];
    __shared__ float sc[64], sh[64];
    for (int i = threadIdx.x; i < 64 * 64; i += 256) As[i] = A[i];
    if (threadIdx.x < 64) {
        sc[threadIdx.x] = g_bnA[h * 64 + threadIdx.x];
        sh[threadIdx.x] = g_bnB[h * 64 + threadIdx.x];
    }
    __syncthreads();

    float acc[64];
    #pragma unroll
    for (int d = 0; d < 64; d++) acc[d] = 0.f;

    #pragma unroll 4
    for (int e = 0; e < 64; e++) {
        float gv = __half2float(Gb[(size_t)e * NN + n]);
        float gn = gv * sc[e] + sh[e];
        float gate = gn / (1.f + __expf(-gn));
        float ve = __half2float(Vb[(size_t)e * NN + n]) * gate;
        #pragma unroll
        for (int d = 0; d < 64; d++) acc[d] += As[d * 64 + e] * ve;
    }
    #pragma unroll
    for (int d = 0; d < 64; d++) Ob[(size_t)d * NN + n] = __float2half_rn(acc[d]);
}

// ---------------- launch ----------------
extern "C" void kernel_launch(void* const* d_in, const int* in_sizes, int n_in,
                              void* d_out, int out_size)
{
    const float* x     = (const float*)d_in[0];
    const float* Wq    = (const float*)d_in[1];
    const float* Wk    = (const float*)d_in[2];
    const float* Wv    = (const float*)d_in[3];
    const float* dw_w  = (const float*)d_in[4];
    const float* gamma = (const float*)d_in[5];
    const float* beta  = (const float*)d_in[6];
    const float* temp  = (const float*)d_in[7];
    const float* Wp    = (const float*)d_in[8];
    const float* bp    = (const float*)d_in[9];
    float* out = (float*)d_out;

    float *Ab;
    __half *QKVh, *Gh, *Xh, *Wh, *Wph, *Oh;
    cudaGetSymbolAddress((void**)&QKVh, g_QKVh);
    cudaGetSymbolAddress((void**)&Gh,   g_Gh);
    cudaGetSymbolAddress((void**)&Ab,   g_attn);
    cudaGetSymbolAddress((void**)&Xh,   g_Xh);
    cudaGetSymbolAddress((void**)&Wh,   g_Wh);
    cudaGetSymbolAddress((void**)&Wph,  g_Wph);
    cudaGetSymbolAddress((void**)&Oh,   g_Oh);

    zero_bn_kernel<<<1, 512>>>();

    const int nX4 = BB * CC * NN / 4;
    const int nW4 = CC * CC / 4;
    f2h_kernel<<<(nX4 + 255) / 256, 256>>>(x,  Xh, nX4);
    f2h_kernel<<<(nW4 + 255) / 256, 256>>>(Wq, Wh + 0 * (size_t)CC * CC, nW4);
    f2h_kernel<<<(nW4 + 255) / 256, 256>>>(Wk, Wh + 1 * (size_t)CC * CC, nW4);
    f2h_kernel<<<(nW4 + 255) / 256, 256>>>(Wv, Wh + 2 * (size_t)CC * CC, nW4);
    f2h_kernel<<<(nW4 + 255) / 256, 256>>>(Wp, Wph, nW4);

    // fused QKV GEMM: stacked A (1536x512), half output
    gemm_h<__half><<<dim3(NN / 128, 3 * CC / 128, BB), 256>>>(Wh, Xh, QKVh, nullptr);

    dwconv_kernel<<<BB * CC, 256>>>(x, dw_w, Gh);
    bn_finalize_kernel<<<1, 512>>>(gamma, beta);

    attn_kernel<<<BB * HEADS, 128>>>(QKVh, QKVh + BCN, temp, Ab);

    attn_apply_kernel<<<dim3(BB * HEADS, NN / 256), 256>>>(Ab, QKVh + 2 * BCN, Gh, Oh);

    gemm_h<float><<<dim3(NN / 128, CC / 128, BB), 256>>>(Wph, Oh, (float*)out, bp);
}

// round 7
// speedup vs baseline: 4.8954x; 1.4177x over previous
#include <cuda_runtime.h>
#include <cuda_fp16.h>
#include <math.h>
#include <stdint.h>

#define BB 32
#define CC 512
#define NN 1024      // H*W = 32*32
#define HEADS 8
#define HD 64
#define BN_EPS 1e-5f
#define BCN ((size_t)BB * CC * NN)

// ---------------- scratch (device globals; no allocation allowed) ----------------
__device__ __half g_QKVh[3 * BCN];                // Q,K,V half
__device__ __half g_Gh[BCN];                      // dwconv output half
__device__ __half g_Oh[BCN];                      // attention output half
__device__ __half g_Xh[BCN];                      // x in half
__device__ __half g_Wh[3 * (size_t)CC * CC];      // Wq,Wk,Wv stacked half
__device__ __half g_Wph[(size_t)CC * CC];         // Wp half
__device__ __half g_attnh[(size_t)BB * HEADS * HD * HD];
__device__ float  g_bnsum[CC];
__device__ float  g_bnsum2[CC];
__device__ float  g_bnA[CC];
__device__ float  g_bnB[CC];

// ============================ helpers ============================
__device__ __forceinline__ uint32_t smem_u32(const void* p) {
    uint32_t a;
    asm("{ .reg .u64 t; cvta.to.shared.u64 t, %1; cvt.u32.u64 %0, t; }" : "=r"(a) : "l"(p));
    return a;
}
__device__ __forceinline__ void cp_async16(uint32_t dst, const void* src) {
    asm volatile("cp.async.cg.shared.global [%0], [%1], 16;" :: "r"(dst), "l"(src));
}
#define CP_COMMIT() asm volatile("cp.async.commit_group;" ::: "memory")
#define CP_WAIT(n)  asm volatile("cp.async.wait_group %0;" :: "n"(n) : "memory")

__device__ __forceinline__ void ldsm4(uint32_t* r, uint32_t addr) {
    asm volatile("ldmatrix.sync.aligned.m8n8.x4.shared.b16 {%0,%1,%2,%3}, [%4];"
        : "=r"(r[0]), "=r"(r[1]), "=r"(r[2]), "=r"(r[3]) : "r"(addr));
}
__device__ __forceinline__ void ldsm4t(uint32_t* r, uint32_t addr) {
    asm volatile("ldmatrix.sync.aligned.m8n8.x4.trans.shared.b16 {%0,%1,%2,%3}, [%4];"
        : "=r"(r[0]), "=r"(r[1]), "=r"(r[2]), "=r"(r[3]) : "r"(addr));
}
__device__ __forceinline__ void mma_f16(float* c, const uint32_t* a, const uint32_t* b) {
    asm volatile("mma.sync.aligned.m16n8k16.row.col.f32.f16.f16.f32 "
        "{%0,%1,%2,%3}, {%4,%5,%6,%7}, {%8,%9}, {%0,%1,%2,%3};"
        : "+f"(c[0]), "+f"(c[1]), "+f"(c[2]), "+f"(c[3])
        : "r"(a[0]), "r"(a[1]), "r"(a[2]), "r"(a[3]), "r"(b[0]), "r"(b[1]));
}

// ============================ small kernels ============================
__global__ void zero_bn_kernel() {
    int t = threadIdx.x;
    if (t < CC) { g_bnsum[t] = 0.f; g_bnsum2[t] = 0.f; }
}

__global__ void bn_finalize_kernel(const float* __restrict__ gamma,
                                   const float* __restrict__ beta) {
    int c = threadIdx.x;
    if (c < CC) {
        const float cnt = (float)(BB * NN);
        float mean = g_bnsum[c] / cnt;
        float var  = g_bnsum2[c] / cnt - mean * mean;
        float A = gamma[c] * rsqrtf(var + BN_EPS);
        g_bnA[c] = A;
        g_bnB[c] = beta[c] - mean * A;
    }
}

// convert 4 weight matrices in one launch
__global__ __launch_bounds__(256)
void f2h_w_kernel(const float* __restrict__ wq, const float* __restrict__ wk,
                  const float* __restrict__ wv, const float* __restrict__ wp,
                  __half* __restrict__ wh, __half* __restrict__ wph)
{
    const int n4 = CC * CC / 4;
    int i = blockIdx.x * 256 + threadIdx.x;   // 0 .. 4*n4-1
    int m = i / n4, r = i - m * n4;
    const float* src = (m == 0) ? wq : (m == 1) ? wk : (m == 2) ? wv : wp;
    __half* dst = (m < 3) ? (wh + (size_t)m * CC * CC) : wph;
    float4 v = ((const float4*)src)[r];
    __half2* o = (__half2*)dst;
    o[2 * r]     = __floats2half2_rn(v.x, v.y);
    o[2 * r + 1] = __floats2half2_rn(v.z, v.w);
}

// ---- fp16 tensor GEMM, templated output type ----
#define ASTRH 40
#define BSTRH 136
template <typename OT>
__global__ __launch_bounds__(256)
void gemm_h(const __half* __restrict__ A, const __half* __restrict__ Bh,
            OT* __restrict__ Y, const float* __restrict__ bias)
{
    __shared__ __half As[2][128 * ASTRH];
    __shared__ __half Bs[2][32 * BSTRH];

    const int t    = threadIdx.x;
    const int lane = t & 31;
    const int wid  = t >> 5;
    const int wm   = wid & 3;
    const int wn   = wid >> 2;
    const int m0g  = blockIdx.y * 128;
    const int mat  = m0g >> 9;
    const int mrow0 = m0g & 511;
    const int n0   = blockIdx.x * 128;
    const int b    = blockIdx.z;

    const __half* Ag = A + (size_t)m0g * CC;
    const __half* Bg = Bh + (size_t)b * CC * NN + n0;
    OT*           Yb = Y + (size_t)mat * BCN + (size_t)b * CC * NN;

    const uint32_t AsU[2] = { smem_u32(As[0]), smem_u32(As[1]) };
    const uint32_t BsU[2] = { smem_u32(Bs[0]), smem_u32(Bs[1]) };

    float acc[2][8][4];
    #pragma unroll
    for (int i = 0; i < 2; i++)
        #pragma unroll
        for (int j = 0; j < 8; j++)
            #pragma unroll
            for (int q = 0; q < 4; q++) acc[i][j][q] = 0.f;

    auto ld_stage = [&](int s, int k0) {
        #pragma unroll
        for (int i = 0; i < 2; i++) {
            int idx = t + 256 * i;
            int r = idx >> 2, j = idx & 3;
            cp_async16(AsU[s] + (uint32_t)(r * ASTRH + j * 8) * 2u,
                       Ag + (size_t)r * CC + k0 + j * 8);
        }
        #pragma unroll
        for (int i = 0; i < 2; i++) {
            int idx = t + 256 * i;
            int r = idx >> 4, j = idx & 15;
            cp_async16(BsU[s] + (uint32_t)(r * BSTRH + j * 8) * 2u,
                       Bg + (size_t)(k0 + r) * NN + j * 8);
        }
    };

    ld_stage(0, 0);
    CP_COMMIT();

    const int gid = lane >> 2, tig = lane & 3;
    const int arow = lane & 15, achk = lane >> 4;

    for (int c = 0; c < 16; c++) {
        if (c < 15) { ld_stage((c + 1) & 1, (c + 1) * 32); CP_COMMIT(); CP_WAIT(1); }
        else        { CP_WAIT(0); }
        __syncthreads();

        const uint32_t Au = AsU[c & 1];
        const uint32_t Bu = BsU[c & 1];

        #pragma unroll
        for (int ks = 0; ks < 2; ks++) {
            uint32_t ra[2][4];
            #pragma unroll
            for (int mi = 0; mi < 2; mi++) {
                int row = wm * 32 + mi * 16 + arow;
                ldsm4(ra[mi], Au + (uint32_t)(row * ASTRH + ks * 16 + achk * 8) * 2u);
            }
            uint32_t rb[4][4];
            #pragma unroll
            for (int nb = 0; nb < 4; nb++) {
                int krow = ks * 16 + arow;
                int col  = wn * 64 + nb * 16 + achk * 8;
                ldsm4t(rb[nb], Bu + (uint32_t)(krow * BSTRH + col) * 2u);
            }
            #pragma unroll
            for (int mi = 0; mi < 2; mi++)
                #pragma unroll
                for (int j = 0; j < 8; j++)
                    mma_f16(acc[mi][j], ra[mi], &rb[j >> 1][(j & 1) * 2]);
        }
        __syncthreads();
    }

    #pragma unroll
    for (int i = 0; i < 2; i++) {
        int ml = mrow0 + wm * 32 + i * 16 + gid;
        float b0 = bias ? bias[ml] : 0.f;
        float b1 = bias ? bias[ml + 8] : 0.f;
        OT* r0 = Yb + (size_t)ml * NN + n0 + wn * 64;
        OT* r1 = r0 + 8 * NN;
        #pragma unroll
        for (int j = 0; j < 8; j++) {
            int cb = j * 8 + 2 * tig;
            if constexpr (sizeof(OT) == 4) {
                *(float2*)((float*)r0 + cb) = make_float2(acc[i][j][0] + b0, acc[i][j][1] + b0);
                *(float2*)((float*)r1 + cb) = make_float2(acc[i][j][2] + b1, acc[i][j][3] + b1);
            } else {
                *(__half2*)((__half*)r0 + cb) = __floats2half2_rn(acc[i][j][0] + b0, acc[i][j][1] + b0);
                *(__half2*)((__half*)r1 + cb) = __floats2half2_rn(acc[i][j][2] + b1, acc[i][j][3] + b1);
            }
        }
    }
}

// ---- attn = softmax( (Q K^T)/(|q||k|) * temp ) per (b,h), tensor-core gram, half out ----
#define QSTR 72
__global__ __launch_bounds__(128)
void attn_kernel(const __half* __restrict__ Q, const __half* __restrict__ K,
                 const float* __restrict__ temp, __half* __restrict__ attn)
{
    const int bh = blockIdx.x;
    const int b = bh / HEADS, h = bh % HEADS;
    const __half* Qb = Q + (size_t)b * CC * NN + (size_t)h * HD * NN;
    const __half* Kb = K + (size_t)b * CC * NN + (size_t)h * HD * NN;

    __shared__ __half Qs[64 * QSTR];
    __shared__ __half Ks[64 * QSTR];
    __shared__ float Ss[64 * 65];
    __shared__ float ssq[64], ssk[64], inv_q[64], inv_k[64];

    const int t = threadIdx.x;
    const int lane = t & 31;
    const int wid = t >> 5;
    const int wm = wid >> 1, wn = wid & 1;

    if (t < 64) { ssq[t] = 0.f; ssk[t] = 0.f; }
    __syncthreads();

    const uint32_t QsU = smem_u32(Qs), KsU = smem_u32(Ks);

    float acc[2][4][4];
    #pragma unroll
    for (int mi = 0; mi < 2; mi++)
        #pragma unroll
        for (int j = 0; j < 4; j++)
            #pragma unroll
            for (int q = 0; q < 4; q++) acc[mi][j][q] = 0.f;

    for (int ch = 0; ch < 16; ch++) {
        const int n0 = ch * 64;
        #pragma unroll
        for (int i = 0; i < 4; i++) {
            int c = t + 128 * i;
            int r = c >> 3, j = c & 7;
            uint4 v = *(const uint4*)(Qb + (size_t)r * NN + n0 + j * 8);
            *(uint4*)&Qs[r * QSTR + j * 8] = v;
            const __half2* hp = (const __half2*)&v;
            float s = 0.f;
            #pragma unroll
            for (int q = 0; q < 4; q++) { float2 f = __half22float2(hp[q]); s += f.x * f.x + f.y * f.y; }
            atomicAdd(&ssq[r], s);
            uint4 w = *(const uint4*)(Kb + (size_t)r * NN + n0 + j * 8);
            *(uint4*)&Ks[r * QSTR + j * 8] = w;
            const __half2* hq = (const __half2*)&w;
            float s2 = 0.f;
            #pragma unroll
            for (int q = 0; q < 4; q++) { float2 f = __half22float2(hq[q]); s2 += f.x * f.x + f.y * f.y; }
            atomicAdd(&ssk[r], s2);
        }
        __syncthreads();

        #pragma unroll
        for (int ks = 0; ks < 4; ks++) {
            uint32_t ra[2][4], rb[2][4];
            #pragma unroll
            for (int mi = 0; mi < 2; mi++)
                ldsm4(ra[mi], QsU + (uint32_t)((wm * 32 + mi * 16 + (lane & 15)) * QSTR
                                               + ks * 16 + (lane >> 4) * 8) * 2u);
            #pragma unroll
            for (int nb = 0; nb < 2; nb++)
                ldsm4(rb[nb], KsU + (uint32_t)((wn * 32 + nb * 16 + (lane & 15)) * QSTR
                                               + ks * 16 + (lane >> 4) * 8) * 2u);
            #pragma unroll
            for (int mi = 0; mi < 2; mi++)
                #pragma unroll
                for (int j = 0; j < 4; j++) {
                    uint32_t bb[2] = { rb[j >> 1][j & 1], rb[j >> 1][(j & 1) + 2] };
                    mma_f16(acc[mi][j], ra[mi], bb);
                }
        }
        __syncthreads();
    }

    if (t < 64) {
        inv_q[t] = 1.f / fmaxf(sqrtf(ssq[t]), 1e-12f);
        inv_k[t] = 1.f / fmaxf(sqrtf(ssk[t]), 1e-12f);
    }
    __syncthreads();

    const float tmp = temp[h];
    const int gid = lane >> 2, tig = lane & 3;
    #pragma unroll
    for (int mi = 0; mi < 2; mi++)
        #pragma unroll
        for (int j = 0; j < 4; j++)
            #pragma unroll
            for (int q = 0; q < 4; q++) {
                int m = wm * 32 + mi * 16 + gid + ((q >> 1) << 3);
                int n = wn * 32 + j * 8 + 2 * tig + (q & 1);
                Ss[m * 65 + n] = acc[mi][j][q] * inv_q[m] * inv_k[n] * tmp;
            }
    __syncthreads();

    if (t < 64) {
        float mx = -1e30f;
        #pragma unroll 8
        for (int e = 0; e < 64; e++) mx = fmaxf(mx, Ss[t * 65 + e]);
        float sum = 0.f;
        #pragma unroll 8
        for (int e = 0; e < 64; e++) {
            float ev = __expf(Ss[t * 65 + e] - mx);
            Ss[t * 65 + e] = ev; sum += ev;
        }
        float inv = 1.f / sum;
        __half* out = attn + ((size_t)bh * HD + t) * HD;
        #pragma unroll 8
        for (int e = 0; e < 64; e += 2)
            *(__half2*)(out + e) = __floats2half2_rn(Ss[t * 65 + e] * inv,
                                                     Ss[t * 65 + e + 1] * inv);
    }
}

// ---------------- depthwise 3x3 conv (half out) + x->half + per-channel stats ----------------
__global__ __launch_bounds__(256)
void dwconv_kernel(const float* __restrict__ x, const float* __restrict__ dw,
                   __half* __restrict__ g, __half* __restrict__ xh)
{
    const int bc = blockIdx.x;
    const int c = bc % CC;
    const float* img = x + (size_t)bc * NN;

    __shared__ float sm[34][34];
    const int t = threadIdx.x;
    for (int i = t; i < 34 * 34; i += 256) {
        int yy = i / 34 - 1, xx = i % 34 - 1;
        sm[i / 34][i % 34] =
            (yy >= 0 && yy < 32 && xx >= 0 && xx < 32) ? img[yy * 32 + xx] : 0.f;
    }
    float w[9];
    #pragma unroll
    for (int i = 0; i < 9; i++) w[i] = dw[c * 9 + i];
    __syncthreads();

    float s = 0.f, s2 = 0.f;
    for (int p = t; p < NN; p += 256) {
        int y = p >> 5, xx = p & 31;
        float acc = 0.f;
        #pragma unroll
        for (int dy = 0; dy < 3; dy++)
            #pragma unroll
            for (int dx = 0; dx < 3; dx++)
                acc += sm[y + dy][xx + dx] * w[dy * 3 + dx];
        g[(size_t)bc * NN + p] = __float2half_rn(acc);
        xh[(size_t)bc * NN + p] = __float2half_rn(sm[y + 1][xx + 1]);
        s += acc; s2 += acc * acc;
    }

    __shared__ float r1[256], r2[256];
    r1[t] = s; r2[t] = s2; __syncthreads();
    for (int st = 128; st > 0; st >>= 1) {
        if (t < st) { r1[t] += r1[t + st]; r2[t] += r2[t + st]; }
        __syncthreads();
    }
    if (t == 0) { atomicAdd(&g_bnsum[c], r1[0]); atomicAdd(&g_bnsum2[c], r2[0]); }
}

// ---- tensorized: O[b,h](64 x 128chunk) = attn(64x64,half) @ (V*silu(bn(G)))(64x128) ----
#define VSTR 136
__global__ __launch_bounds__(128)
void attn_apply_kernel(const __half* __restrict__ attn, const __half* __restrict__ v,
                       const __half* __restrict__ gbuf, __half* __restrict__ o)
{
    const int bh = blockIdx.x;
    const int nc = blockIdx.y;                    // 0..7, chunk of 128 cols
    const int b = bh / HEADS, h = bh % HEADS;
    const __half* A  = attn + (size_t)bh * HD * HD;
    const __half* Vb = v    + (size_t)b * CC * NN + (size_t)h * HD * NN + nc * 128;
    const __half* Gb = gbuf + (size_t)b * CC * NN + (size_t)h * HD * NN + nc * 128;
    __half*       Ob = o    + (size_t)b * CC * NN + (size_t)h * HD * NN + nc * 128;

    __shared__ __half Ah[64 * QSTR];
    __shared__ __half Bsm[64 * VSTR];
    __shared__ float sc[64], sh[64];

    const int t = threadIdx.x;
    const int lane = t & 31;
    const int w = t >> 5;                         // warp 0..3 -> n cols [w*32, w*32+32)

    if (t < 64) {
        sc[t] = g_bnA[h * 64 + t];
        sh[t] = g_bnB[h * 64 + t];
    }
    // attn 64x64 halves -> Ah (padded rows)
    #pragma unroll
    for (int i = 0; i < 4; i++) {
        int cidx = t + 128 * i;
        int r = cidx >> 3, j = cidx & 7;
        *(uint4*)&Ah[r * QSTR + j * 8] = *(const uint4*)(A + r * 64 + j * 8);
    }
    __syncthreads();

    // gated V tile 64x128 -> Bsm
    #pragma unroll
    for (int i = 0; i < 8; i++) {
        int cidx = t + 128 * i;                   // 0..1023 chunks of 8 halves
        int r = cidx >> 4, j = cidx & 15;
        uint4 vv = *(const uint4*)(Vb + (size_t)r * NN + j * 8);
        uint4 gg = *(const uint4*)(Gb + (size_t)r * NN + j * 8);
        const float Ac = sc[r], Bc = sh[r];
        __half2 res[4];
        const __half2* vp = (const __half2*)&vv;
        const __half2* gp = (const __half2*)&gg;
        #pragma unroll
        for (int q = 0; q < 4; q++) {
            float2 gf = __half22float2(gp[q]);
            float2 vf = __half22float2(vp[q]);
            float gn0 = gf.x * Ac + Bc, gn1 = gf.y * Ac + Bc;
            float gt0 = gn0 / (1.f + __expf(-gn0));
            float gt1 = gn1 / (1.f + __expf(-gn1));
            res[q] = __floats2half2_rn(vf.x * gt0, vf.y * gt1);
        }
        *(uint4*)&Bsm[r * VSTR + j * 8] = *(uint4*)res;
    }
    __syncthreads();

    const uint32_t AhU = smem_u32(Ah), BsU = smem_u32(Bsm);
    const int arow = lane & 15, achk = lane >> 4;
    const int gid = lane >> 2, tig = lane & 3;

    float acc[4][4][4];
    #pragma unroll
    for (int mi = 0; mi < 4; mi++)
        #pragma unroll
        for (int j = 0; j < 4; j++)
            #pragma unroll
            for (int q = 0; q < 4; q++) acc[mi][j][q] = 0.f;

    #pragma unroll
    for (int ks = 0; ks < 4; ks++) {
        uint32_t ra[4][4];
        #pragma unroll
        for (int mi = 0; mi < 4; mi++)
            ldsm4(ra[mi], AhU + (uint32_t)((mi * 16 + arow) * QSTR + ks * 16 + achk * 8) * 2u);
        uint32_t rb[2][4];
        #pragma unroll
        for (int nb = 0; nb < 2; nb++)
            ldsm4t(rb[nb], BsU + (uint32_t)((ks * 16 + arow) * VSTR + w * 32 + nb * 16 + achk * 8) * 2u);
        #pragma unroll
        for (int mi = 0; mi < 4; mi++)
            #pragma unroll
            for (int j = 0; j < 4; j++)
                mma_f16(acc[mi][j], ra[mi], &rb[j >> 1][(j & 1) * 2]);
    }

    #pragma unroll
    for (int mi = 0; mi < 4; mi++) {
        int row0 = mi * 16 + gid;
        #pragma unroll
        for (int j = 0; j < 4; j++) {
            int coln = w * 32 + j * 8 + 2 * tig;
            *(__half2*)(Ob + (size_t)row0 * NN + coln) =
                __floats2half2_rn(acc[mi][j][0], acc[mi][j][1]);
            *(__half2*)(Ob + (size_t)(row0 + 8) * NN + coln) =
                __floats2half2_rn(acc[mi][j][2], acc[mi][j][3]);
        }
    }
}

// ---------------- launch ----------------
extern "C" void kernel_launch(void* const* d_in, const int* in_sizes, int n_in,
                              void* d_out, int out_size)
{
    const float* x     = (const float*)d_in[0];
    const float* Wq    = (const float*)d_in[1];
    const float* Wk    = (const float*)d_in[2];
    const float* Wv    = (const float*)d_in[3];
    const float* dw_w  = (const float*)d_in[4];
    const float* gamma = (const float*)d_in[5];
    const float* beta  = (const float*)d_in[6];
    const float* temp  = (const float*)d_in[7];
    const float* Wp    = (const float*)d_in[8];
    const float* bp    = (const float*)d_in[9];
    float* out = (float*)d_out;

    __half *QKVh, *Gh, *Xh, *Wh, *Wph, *Oh, *Ah;
    cudaGetSymbolAddress((void**)&QKVh, g_QKVh);
    cudaGetSymbolAddress((void**)&Gh,   g_Gh);
    cudaGetSymbolAddress((void**)&Ah,   g_attnh);
    cudaGetSymbolAddress((void**)&Xh,   g_Xh);
    cudaGetSymbolAddress((void**)&Wh,   g_Wh);
    cudaGetSymbolAddress((void**)&Wph,  g_Wph);
    cudaGetSymbolAddress((void**)&Oh,   g_Oh);

    zero_bn_kernel<<<1, 512>>>();

    // dwconv: G (half), Xh (half), BN partial sums — single pass over x
    dwconv_kernel<<<BB * CC, 256>>>(x, dw_w, Gh, Xh);

    const int nW4all = 4 * CC * CC / 4;
    f2h_w_kernel<<<(nW4all + 255) / 256, 256>>>(Wq, Wk, Wv, Wp, Wh, Wph);

    // fused QKV GEMM: stacked A (1536x512), half output
    gemm_h<__half><<<dim3(NN / 128, 3 * CC / 128, BB), 256>>>(Wh, Xh, QKVh, nullptr);

    bn_finalize_kernel<<<1, 512>>>(gamma, beta);

    attn_kernel<<<BB * HEADS, 128>>>(QKVh, QKVh + BCN, temp, Ah);

    attn_apply_kernel<<<dim3(BB * HEADS, NN / 128), 128>>>(Ah, QKVh + 2 * BCN, Gh, Oh);

    gemm_h<float><<<dim3(NN / 128, CC / 128, BB), 256>>>(Wph, Oh, (float*)out, bp);
}

// round 8
// speedup vs baseline: 6.0527x; 1.2364x over previous
#include <cuda_runtime.h>
#include <cuda_fp16.h>
#include <math.h>
#include <stdint.h>

#define BB 32
#define CC 512
#define NN 1024      // H*W = 32*32
#define HEADS 8
#define HD 64
#define BN_EPS 1e-5f
#define BCN ((size_t)BB * CC * NN)

// ---------------- scratch (device globals; no allocation allowed) ----------------
__device__ __half g_QKVh[3 * BCN];                // Q,K,V half
__device__ __half g_Gh[BCN];                      // dwconv output half
__device__ __half g_Oh[BCN];                      // attention output half
__device__ __half g_Xh[BCN];                      // x in half
__device__ __half g_Wh[3 * (size_t)CC * CC];      // Wq,Wk,Wv stacked half
__device__ __half g_Wph[(size_t)CC * CC];         // Wp half
__device__ __half g_attnh[(size_t)BB * HEADS * HD * HD];
__device__ float  g_bnsum[CC];
__device__ float  g_bnsum2[CC];
__device__ float  g_bnA[CC];
__device__ float  g_bnB[CC];

// ============================ helpers ============================
__device__ __forceinline__ uint32_t smem_u32(const void* p) {
    uint32_t a;
    asm("{ .reg .u64 t; cvta.to.shared.u64 t, %1; cvt.u32.u64 %0, t; }" : "=r"(a) : "l"(p));
    return a;
}
__device__ __forceinline__ void cp_async16(uint32_t dst, const void* src) {
    asm volatile("cp.async.cg.shared.global [%0], [%1], 16;" :: "r"(dst), "l"(src));
}
#define CP_COMMIT() asm volatile("cp.async.commit_group;" ::: "memory")
#define CP_WAIT(n)  asm volatile("cp.async.wait_group %0;" :: "n"(n) : "memory")

__device__ __forceinline__ void ldsm4(uint32_t* r, uint32_t addr) {
    asm volatile("ldmatrix.sync.aligned.m8n8.x4.shared.b16 {%0,%1,%2,%3}, [%4];"
        : "=r"(r[0]), "=r"(r[1]), "=r"(r[2]), "=r"(r[3]) : "r"(addr));
}
__device__ __forceinline__ void ldsm4t(uint32_t* r, uint32_t addr) {
    asm volatile("ldmatrix.sync.aligned.m8n8.x4.trans.shared.b16 {%0,%1,%2,%3}, [%4];"
        : "=r"(r[0]), "=r"(r[1]), "=r"(r[2]), "=r"(r[3]) : "r"(addr));
}
__device__ __forceinline__ void mma_f16(float* c, const uint32_t* a, const uint32_t* b) {
    asm volatile("mma.sync.aligned.m16n8k16.row.col.f32.f16.f16.f32 "
        "{%0,%1,%2,%3}, {%4,%5,%6,%7}, {%8,%9}, {%0,%1,%2,%3};"
        : "+f"(c[0]), "+f"(c[1]), "+f"(c[2]), "+f"(c[3])
        : "r"(a[0]), "r"(a[1]), "r"(a[2]), "r"(a[3]), "r"(b[0]), "r"(b[1]));
}

// ============================ small kernels ============================
__global__ void zero_bn_kernel() {
    int t = threadIdx.x;
    if (t < CC) { g_bnsum[t] = 0.f; g_bnsum2[t] = 0.f; }
}

__global__ void bn_finalize_kernel(const float* __restrict__ gamma,
                                   const float* __restrict__ beta) {
    int c = threadIdx.x;
    if (c < CC) {
        const float cnt = (float)(BB * NN);
        float mean = g_bnsum[c] / cnt;
        float var  = g_bnsum2[c] / cnt - mean * mean;
        float A = gamma[c] * rsqrtf(var + BN_EPS);
        g_bnA[c] = A;
        g_bnB[c] = beta[c] - mean * A;
    }
}

__global__ __launch_bounds__(256)
void f2h_w_kernel(const float* __restrict__ wq, const float* __restrict__ wk,
                  const float* __restrict__ wv, const float* __restrict__ wp,
                  __half* __restrict__ wh, __half* __restrict__ wph)
{
    const int n4 = CC * CC / 4;
    int i = blockIdx.x * 256 + threadIdx.x;
    int m = i / n4, r = i - m * n4;
    const float* src = (m == 0) ? wq : (m == 1) ? wk : (m == 2) ? wv : wp;
    __half* dst = (m < 3) ? (wh + (size_t)m * CC * CC) : wph;
    float4 v = ((const float4*)src)[r];
    __half2* o = (__half2*)dst;
    o[2 * r]     = __floats2half2_rn(v.x, v.y);
    o[2 * r + 1] = __floats2half2_rn(v.z, v.w);
}

// ---- fp16 tensor GEMM, 4-stage cp.async pipeline, single barrier/chunk ----
#define ASTRH 40
#define BSTRH 136
#define STAGES 4
#define A_STAGE_BYTES (128 * ASTRH * 2)           // 10240
#define B_STAGE_BYTES (32 * BSTRH * 2)            // 8704
#define STAGE_BYTES (A_STAGE_BYTES + B_STAGE_BYTES)   // 18944
#define GEMM_SMEM (STAGES * STAGE_BYTES)          // 75776

template <typename OT>
__global__ __launch_bounds__(256)
void gemm_h(const __half* __restrict__ A, const __half* __restrict__ Bh,
            OT* __restrict__ Y, const float* __restrict__ bias)
{
    extern __shared__ __half dsm[];
    const uint32_t base = smem_u32(dsm);

    const int t    = threadIdx.x;
    const int lane = t & 31;
    const int wid  = t >> 5;
    const int wm   = wid & 3;
    const int wn   = wid >> 2;
    const int m0g  = blockIdx.y * 128;
    const int mat  = m0g >> 9;
    const int mrow0 = m0g & 511;
    const int n0   = blockIdx.x * 128;
    const int b    = blockIdx.z;

    const __half* Ag = A + (size_t)m0g * CC;
    const __half* Bg = Bh + (size_t)b * CC * NN + n0;
    OT*           Yb = Y + (size_t)mat * BCN + (size_t)b * CC * NN;

    float acc[2][8][4];
    #pragma unroll
    for (int i = 0; i < 2; i++)
        #pragma unroll
        for (int j = 0; j < 8; j++)
            #pragma unroll
            for (int q = 0; q < 4; q++) acc[i][j][q] = 0.f;

    auto ld_stage = [&](int s, int k0) {
        const uint32_t au = base + (uint32_t)s * STAGE_BYTES;
        const uint32_t bu = au + A_STAGE_BYTES;
        #pragma unroll
        for (int i = 0; i < 2; i++) {
            int idx = t + 256 * i;
            int r = idx >> 2, j = idx & 3;
            cp_async16(au + (uint32_t)(r * ASTRH + j * 8) * 2u,
                       Ag + (size_t)r * CC + k0 + j * 8);
        }
        #pragma unroll
        for (int i = 0; i < 2; i++) {
            int idx = t + 256 * i;
            int r = idx >> 4, j = idx & 15;
            cp_async16(bu + (uint32_t)(r * BSTRH + j * 8) * 2u,
                       Bg + (size_t)(k0 + r) * NN + j * 8);
        }
    };

    #pragma unroll
    for (int s = 0; s < STAGES - 1; s++) { ld_stage(s, s * 32); CP_COMMIT(); }

    const int gid = lane >> 2, tig = lane & 3;
    const int arow = lane & 15, achk = lane >> 4;

    for (int c = 0; c < 16; c++) {
        CP_WAIT(STAGES - 2);
        __syncthreads();

        const uint32_t Au = base + (uint32_t)(c & (STAGES - 1)) * STAGE_BYTES;
        const uint32_t Bu = Au + A_STAGE_BYTES;

        #pragma unroll
        for (int ks = 0; ks < 2; ks++) {
            uint32_t ra[2][4];
            #pragma unroll
            for (int mi = 0; mi < 2; mi++) {
                int row = wm * 32 + mi * 16 + arow;
                ldsm4(ra[mi], Au + (uint32_t)(row * ASTRH + ks * 16 + achk * 8) * 2u);
            }
            uint32_t rb[4][4];
            #pragma unroll
            for (int nb = 0; nb < 4; nb++) {
                int krow = ks * 16 + arow;
                int col  = wn * 64 + nb * 16 + achk * 8;
                ldsm4t(rb[nb], Bu + (uint32_t)(krow * BSTRH + col) * 2u);
            }
            #pragma unroll
            for (int mi = 0; mi < 2; mi++)
                #pragma unroll
                for (int j = 0; j < 8; j++)
                    mma_f16(acc[mi][j], ra[mi], &rb[j >> 1][(j & 1) * 2]);
        }

        if (c + STAGES - 1 < 16) ld_stage((c + STAGES - 1) & (STAGES - 1),
                                          (c + STAGES - 1) * 32);
        CP_COMMIT();
    }

    #pragma unroll
    for (int i = 0; i < 2; i++) {
        int ml = mrow0 + wm * 32 + i * 16 + gid;
        float b0 = bias ? bias[ml] : 0.f;
        float b1 = bias ? bias[ml + 8] : 0.f;
        OT* r0 = Yb + (size_t)ml * NN + n0 + wn * 64;
        OT* r1 = r0 + 8 * NN;
        #pragma unroll
        for (int j = 0; j < 8; j++) {
            int cb = j * 8 + 2 * tig;
            if constexpr (sizeof(OT) == 4) {
                *(float2*)((float*)r0 + cb) = make_float2(acc[i][j][0] + b0, acc[i][j][1] + b0);
                *(float2*)((float*)r1 + cb) = make_float2(acc[i][j][2] + b1, acc[i][j][3] + b1);
            } else {
                *(__half2*)((__half*)r0 + cb) = __floats2half2_rn(acc[i][j][0] + b0, acc[i][j][1] + b0);
                *(__half2*)((__half*)r1 + cb) = __floats2half2_rn(acc[i][j][2] + b1, acc[i][j][3] + b1);
            }
        }
    }
}

// ---- attn = softmax( (Q K^T)/(|q||k|) * temp ) per (b,h), tensor-core gram, half out ----
#define QSTR 72
__global__ __launch_bounds__(128)
void attn_kernel(const __half* __restrict__ Q, const __half* __restrict__ K,
                 const float* __restrict__ temp, __half* __restrict__ attn)
{
    const int bh = blockIdx.x;
    const int b = bh / HEADS, h = bh % HEADS;
    const __half* Qb = Q + (size_t)b * CC * NN + (size_t)h * HD * NN;
    const __half* Kb = K + (size_t)b * CC * NN + (size_t)h * HD * NN;

    __shared__ __half Qs[64 * QSTR];
    __shared__ __half Ks[64 * QSTR];
    __shared__ float Ss[64 * 65];
    __shared__ float ssq[64], ssk[64], inv_q[64], inv_k[64];

    const int t = threadIdx.x;
    const int lane = t & 31;
    const int wid = t >> 5;
    const int wm = wid >> 1, wn = wid & 1;

    if (t < 64) { ssq[t] = 0.f; ssk[t] = 0.f; }
    __syncthreads();

    const uint32_t QsU = smem_u32(Qs), KsU = smem_u32(Ks);

    float acc[2][4][4];
    #pragma unroll
    for (int mi = 0; mi < 2; mi++)
        #pragma unroll
        for (int j = 0; j < 4; j++)
            #pragma unroll
            for (int q = 0; q < 4; q++) acc[mi][j][q] = 0.f;

    float accq4[4] = {0.f, 0.f, 0.f, 0.f};
    float acck4[4] = {0.f, 0.f, 0.f, 0.f};

    for (int ch = 0; ch < 16; ch++) {
        const int n0 = ch * 64;
        #pragma unroll
        for (int i = 0; i < 4; i++) {
            int c = t + 128 * i;
            int r = c >> 3, j = c & 7;
            uint4 v = *(const uint4*)(Qb + (size_t)r * NN + n0 + j * 8);
            *(uint4*)&Qs[r * QSTR + j * 8] = v;
            const __half2* hp = (const __half2*)&v;
            #pragma unroll
            for (int q = 0; q < 4; q++) { float2 f = __half22float2(hp[q]); accq4[i] += f.x * f.x + f.y * f.y; }
            uint4 w = *(const uint4*)(Kb + (size_t)r * NN + n0 + j * 8);
            *(uint4*)&Ks[r * QSTR + j * 8] = w;
            const __half2* hq = (const __half2*)&w;
            #pragma unroll
            for (int q = 0; q < 4; q++) { float2 f = __half22float2(hq[q]); acck4[i] += f.x * f.x + f.y * f.y; }
        }
        __syncthreads();

        #pragma unroll
        for (int ks = 0; ks < 4; ks++) {
            uint32_t ra[2][4], rb[2][4];
            #pragma unroll
            for (int mi = 0; mi < 2; mi++)
                ldsm4(ra[mi], QsU + (uint32_t)((wm * 32 + mi * 16 + (lane & 15)) * QSTR
                                               + ks * 16 + (lane >> 4) * 8) * 2u);
            #pragma unroll
            for (int nb = 0; nb < 2; nb++)
                ldsm4(rb[nb], KsU + (uint32_t)((wn * 32 + nb * 16 + (lane & 15)) * QSTR
                                               + ks * 16 + (lane >> 4) * 8) * 2u);
            #pragma unroll
            for (int mi = 0; mi < 2; mi++)
                #pragma unroll
                for (int j = 0; j < 4; j++) {
                    uint32_t bb[2] = { rb[j >> 1][j & 1], rb[j >> 1][(j & 1) + 2] };
                    mma_f16(acc[mi][j], ra[mi], bb);
                }
        }
        __syncthreads();
    }

    #pragma unroll
    for (int i = 0; i < 4; i++) {
        int r = (t + 128 * i) >> 3;
        atomicAdd(&ssq[r], accq4[i]);
        atomicAdd(&ssk[r], acck4[i]);
    }
    __syncthreads();

    if (t < 64) {
        inv_q[t] = 1.f / fmaxf(sqrtf(ssq[t]), 1e-12f);
        inv_k[t] = 1.f / fmaxf(sqrtf(ssk[t]), 1e-12f);
    }
    __syncthreads();

    const float tmp = temp[h];
    const int gid = lane >> 2, tig = lane & 3;
    #pragma unroll
    for (int mi = 0; mi < 2; mi++)
        #pragma unroll
        for (int j = 0; j < 4; j++)
            #pragma unroll
            for (int q = 0; q < 4; q++) {
                int m = wm * 32 + mi * 16 + gid + ((q >> 1) << 3);
                int n = wn * 32 + j * 8 + 2 * tig + (q & 1);
                Ss[m * 65 + n] = acc[mi][j][q] * inv_q[m] * inv_k[n] * tmp;
            }
    __syncthreads();

    if (t < 64) {
        float mx = -1e30f;
        #pragma unroll 8
        for (int e = 0; e < 64; e++) mx = fmaxf(mx, Ss[t * 65 + e]);
        float sum = 0.f;
        #pragma unroll 8
        for (int e = 0; e < 64; e++) {
            float ev = __expf(Ss[t * 65 + e] - mx);
            Ss[t * 65 + e] = ev; sum += ev;
        }
        float inv = 1.f / sum;
        __half* out = attn + ((size_t)bh * HD + t) * HD;
        #pragma unroll 8
        for (int e = 0; e < 64; e += 2)
            *(__half2*)(out + e) = __floats2half2_rn(Ss[t * 65 + e] * inv,
                                                     Ss[t * 65 + e + 1] * inv);
    }
}

// ---------------- depthwise 3x3 conv (half out) + x->half + per-channel stats ----------------
__global__ __launch_bounds__(256)
void dwconv_kernel(const float* __restrict__ x, const float* __restrict__ dw,
                   __half* __restrict__ g, __half* __restrict__ xh)
{
    const int bc = blockIdx.x;
    const int c = bc % CC;
    const float* img = x + (size_t)bc * NN;

    __shared__ float sm[34][34];
    const int t = threadIdx.x;
    for (int i = t; i < 34 * 34; i += 256) {
        int yy = i / 34 - 1, xx = i % 34 - 1;
        sm[i / 34][i % 34] =
            (yy >= 0 && yy < 32 && xx >= 0 && xx < 32) ? img[yy * 32 + xx] : 0.f;
    }
    float w[9];
    #pragma unroll
    for (int i = 0; i < 9; i++) w[i] = dw[c * 9 + i];
    __syncthreads();

    float s = 0.f, s2 = 0.f;
    for (int p = t; p < NN; p += 256) {
        int y = p >> 5, xx = p & 31;
        float acc = 0.f;
        #pragma unroll
        for (int dy = 0; dy < 3; dy++)
            #pragma unroll
            for (int dx = 0; dx < 3; dx++)
                acc += sm[y + dy][xx + dx] * w[dy * 3 + dx];
        g[(size_t)bc * NN + p] = __float2half_rn(acc);
        xh[(size_t)bc * NN + p] = __float2half_rn(sm[y + 1][xx + 1]);
        s += acc; s2 += acc * acc;
    }

    __shared__ float r1[256], r2[256];
    r1[t] = s; r2[t] = s2; __syncthreads();
    for (int st = 128; st > 0; st >>= 1) {
        if (t < st) { r1[t] += r1[t + st]; r2[t] += r2[t + st]; }
        __syncthreads();
    }
    if (t == 0) { atomicAdd(&g_bnsum[c], r1[0]); atomicAdd(&g_bnsum2[c], r2[0]); }
}

// ---- tensorized: O[b,h](64 x 128chunk) = attn(64x64,half) @ (V*silu(bn(G)))(64x128) ----
#define VSTR 136
__global__ __launch_bounds__(128)
void attn_apply_kernel(const __half* __restrict__ attn, const __half* __restrict__ v,
                       const __half* __restrict__ gbuf, __half* __restrict__ o)
{
    const int bh = blockIdx.x;
    const int nc = blockIdx.y;
    const int b = bh / HEADS, h = bh % HEADS;
    const __half* A  = attn + (size_t)bh * HD * HD;
    const __half* Vb = v    + (size_t)b * CC * NN + (size_t)h * HD * NN + nc * 128;
    const __half* Gb = gbuf + (size_t)b * CC * NN + (size_t)h * HD * NN + nc * 128;
    __half*       Ob = o    + (size_t)b * CC * NN + (size_t)h * HD * NN + nc * 128;

    __shared__ __half Ah[64 * QSTR];
    __shared__ __half Bsm[64 * VSTR];
    __shared__ float sc[64], sh[64];

    const int t = threadIdx.x;
    const int lane = t & 31;
    const int w = t >> 5;

    if (t < 64) {
        sc[t] = g_bnA[h * 64 + t];
        sh[t] = g_bnB[h * 64 + t];
    }
    #pragma unroll
    for (int i = 0; i < 4; i++) {
        int cidx = t + 128 * i;
        int r = cidx >> 3, j = cidx & 7;
        *(uint4*)&Ah[r * QSTR + j * 8] = *(const uint4*)(A + r * 64 + j * 8);
    }
    __syncthreads();

    #pragma unroll
    for (int i = 0; i < 8; i++) {
        int cidx = t + 128 * i;
        int r = cidx >> 4, j = cidx & 15;
        uint4 vv = *(const uint4*)(Vb + (size_t)r * NN + j * 8);
        uint4 gg = *(const uint4*)(Gb + (size_t)r * NN + j * 8);
        const float Ac = sc[r], Bc = sh[r];
        __half2 res[4];
        const __half2* vp = (const __half2*)&vv;
        const __half2* gp = (const __half2*)&gg;
        #pragma unroll
        for (int q = 0; q < 4; q++) {
            float2 gf = __half22float2(gp[q]);
            float2 vf = __half22float2(vp[q]);
            float gn0 = gf.x * Ac + Bc, gn1 = gf.y * Ac + Bc;
            float gt0 = gn0 / (1.f + __expf(-gn0));
            float gt1 = gn1 / (1.f + __expf(-gn1));
            res[q] = __floats2half2_rn(vf.x * gt0, vf.y * gt1);
        }
        *(uint4*)&Bsm[r * VSTR + j * 8] = *(uint4*)res;
    }
    __syncthreads();

    const uint32_t AhU = smem_u32(Ah), BsU = smem_u32(Bsm);
    const int arow = lane & 15, achk = lane >> 4;
    const int gid = lane >> 2, tig = lane & 3;

    float acc[4][4][4];
    #pragma unroll
    for (int mi = 0; mi < 4; mi++)
        #pragma unroll
        for (int j = 0; j < 4; j++)
            #pragma unroll
            for (int q = 0; q < 4; q++) acc[mi][j][q] = 0.f;

    #pragma unroll
    for (int ks = 0; ks < 4; ks++) {
        uint32_t ra[4][4];
        #pragma unroll
        for (int mi = 0; mi < 4; mi++)
            ldsm4(ra[mi], AhU + (uint32_t)((mi * 16 + arow) * QSTR + ks * 16 + achk * 8) * 2u);
        uint32_t rb[2][4];
        #pragma unroll
        for (int nb = 0; nb < 2; nb++)
            ldsm4t(rb[nb], BsU + (uint32_t)((ks * 16 + arow) * VSTR + w * 32 + nb * 16 + achk * 8) * 2u);
        #pragma unroll
        for (int mi = 0; mi < 4; mi++)
            #pragma unroll
            for (int j = 0; j < 4; j++)
                mma_f16(acc[mi][j], ra[mi], &rb[j >> 1][(j & 1) * 2]);
    }

    #pragma unroll
    for (int mi = 0; mi < 4; mi++) {
        int row0 = mi * 16 + gid;
        #pragma unroll
        for (int j = 0; j < 4; j++) {
            int coln = w * 32 + j * 8 + 2 * tig;
            *(__half2*)(Ob + (size_t)row0 * NN + coln) =
                __floats2half2_rn(acc[mi][j][0], acc[mi][j][1]);
            *(__half2*)(Ob + (size_t)(row0 + 8) * NN + coln) =
                __floats2half2_rn(acc[mi][j][2], acc[mi][j][3]);
        }
    }
}

// ---------------- launch ----------------
extern "C" void kernel_launch(void* const* d_in, const int* in_sizes, int n_in,
                              void* d_out, int out_size)
{
    const float* x     = (const float*)d_in[0];
    const float* Wq    = (const float*)d_in[1];
    const float* Wk    = (const float*)d_in[2];
    const float* Wv    = (const float*)d_in[3];
    const float* dw_w  = (const float*)d_in[4];
    const float* gamma = (const float*)d_in[5];
    const float* beta  = (const float*)d_in[6];
    const float* temp  = (const float*)d_in[7];
    const float* Wp    = (const float*)d_in[8];
    const float* bp    = (const float*)d_in[9];
    float* out = (float*)d_out;

    __half *QKVh, *Gh, *Xh, *Wh, *Wph, *Oh, *Ah;
    cudaGetSymbolAddress((void**)&QKVh, g_QKVh);
    cudaGetSymbolAddress((void**)&Gh,   g_Gh);
    cudaGetSymbolAddress((void**)&Ah,   g_attnh);
    cudaGetSymbolAddress((void**)&Xh,   g_Xh);
    cudaGetSymbolAddress((void**)&Wh,   g_Wh);
    cudaGetSymbolAddress((void**)&Wph,  g_Wph);
    cudaGetSymbolAddress((void**)&Oh,   g_Oh);

    cudaFuncSetAttribute(gemm_h<__half>, cudaFuncAttributeMaxDynamicSharedMemorySize, GEMM_SMEM);
    cudaFuncSetAttribute(gemm_h<float>,  cudaFuncAttributeMaxDynamicSharedMemorySize, GEMM_SMEM);

    zero_bn_kernel<<<1, 512>>>();

    dwconv_kernel<<<BB * CC, 256>>>(x, dw_w, Gh, Xh);

    const int nW4all = 4 * CC * CC / 4;
    f2h_w_kernel<<<(nW4all + 255) / 256, 256>>>(Wq, Wk, Wv, Wp, Wh, Wph);

    gemm_h<__half><<<dim3(NN / 128, 3 * CC / 128, BB), 256, GEMM_SMEM>>>(Wh, Xh, QKVh, nullptr);

    bn_finalize_kernel<<<1, 512>>>(gamma, beta);

    attn_kernel<<<BB * HEADS, 128>>>(QKVh, QKVh + BCN, temp, Ah);

    attn_apply_kernel<<<dim3(BB * HEADS, NN / 128), 128>>>(Ah, QKVh + 2 * BCN, Gh, Oh);

    gemm_h<float><<<dim3(NN / 128, CC / 128, BB), 256, GEMM_SMEM>>>(Wph, Oh, (float*)out, bp);
}